// round 2
// baseline (speedup 1.0000x reference)
#include <cuda_runtime.h>
#include <cuda_bf16.h>

// Performer (FAVOR+) causal attention, chunked linear-attention decomposition.
// B=8, N=4096, D=256, M=256, DV=256. Chunk C=128, NC=32.
//
// out[t] = (phi_q[t] . S_t) / max(phi_q[t] . z_t, 1e-6)
//   S_t = sum_{i<=t} phi_k[i] (x) v[i],  z_t = sum_{i<=t} phi_k[i]
// phi(x)[m] = exp(proj[m] - rowmax(proj)) / sqrt(M)   (the -0.5||x||^2 term
// cancels against the rowmax shift), proj = x @ omega^T.
//
// Chunked: out = (tril(Pq Pk^T) V + Pq S_pre) / (rowsum(tril(Pq Pk^T)) + Pq z_pre)

#define BATCH 8
#define SEQ   4096
#define DD    256
#define MM    256
#define DVV   256
#define CHUNK 128
#define NCHUNK (SEQ / CHUNK)   // 32
#define KT    16

// Scratch (device globals; no allocation allowed)
__device__ float g_phiQ[BATCH * SEQ * MM];                 // 33.5 MB
__device__ float g_phiK[BATCH * SEQ * MM];                 // 33.5 MB
__device__ float g_S[BATCH * NCHUNK * MM * DVV];           // 67 MB (chunk states -> exclusive prefix)
__device__ float g_z[BATCH * NCHUNK * MM];                 // 256 KB

// ---------------------------------------------------------------------------
// Kernel 1: phi = exp(X @ omega^T - rowmax) / 16  for X in {Q, K_in}.
// Tile: 64 rows x 256 cols per CTA, blockDim (32,8), 8x8 micro per thread.
// rows: e*8+ty (e 0..7), cols: f*32+tx (f 0..7)  -> warp (fixed ty) owns 8 rows
// fully => rowmax via warp shuffle.
// ---------------------------------------------------------------------------
__global__ void __launch_bounds__(256) phi_kernel(const float* __restrict__ Q,
                                                  const float* __restrict__ Kin,
                                                  const float* __restrict__ W)
{
    __shared__ float Xs[KT][65];    // transposed: Xs[k][row]
    __shared__ float Ws[KT][257];   // transposed: Ws[k][m]

    const float* X  = (blockIdx.y == 0) ? Q : Kin;
    float*      Phi = (blockIdx.y == 0) ? g_phiQ : g_phiK;

    const int row0 = blockIdx.x * 64;
    const int tx = threadIdx.x, ty = threadIdx.y;
    const int tid = ty * 32 + tx;

    float acc[8][8];
#pragma unroll
    for (int e = 0; e < 8; e++)
#pragma unroll
        for (int f = 0; f < 8; f++) acc[e][f] = 0.f;

    for (int d0 = 0; d0 < DD; d0 += KT) {
        // Xs: 64 rows x 16 d, store transposed
#pragma unroll
        for (int e = 0; e < 4; e++) {
            int li = tid + e * 256;            // 0..1023
            int r = li >> 4, c = li & 15;
            Xs[c][r] = X[(size_t)(row0 + r) * DD + d0 + c];
        }
        // Ws: 256 m x 16 d, store transposed
#pragma unroll
        for (int e = 0; e < 16; e++) {
            int li = tid + e * 256;            // 0..4095
            int r = li >> 4, c = li & 15;
            Ws[c][r] = W[(size_t)r * DD + d0 + c];
        }
        __syncthreads();
#pragma unroll
        for (int k = 0; k < KT; k++) {
            float a[8], bb[8];
#pragma unroll
            for (int e = 0; e < 8; e++) a[e] = Xs[k][e * 8 + ty];
#pragma unroll
            for (int f = 0; f < 8; f++) bb[f] = Ws[k][f * 32 + tx];
#pragma unroll
            for (int e = 0; e < 8; e++)
#pragma unroll
                for (int f = 0; f < 8; f++) acc[e][f] = fmaf(a[e], bb[f], acc[e][f]);
        }
        __syncthreads();
    }

    // epilogue: per-row max over all 256 cols (8 local + warp shuffle), exp, /16
#pragma unroll
    for (int e = 0; e < 8; e++) {
        float mx = acc[e][0];
#pragma unroll
        for (int f = 1; f < 8; f++) mx = fmaxf(mx, acc[e][f]);
#pragma unroll
        for (int o = 16; o > 0; o >>= 1) mx = fmaxf(mx, __shfl_xor_sync(0xffffffffu, mx, o));
        const size_t rowoff = (size_t)(row0 + e * 8 + ty) * MM;
#pragma unroll
        for (int f = 0; f < 8; f++)
            Phi[rowoff + f * 32 + tx] = __expf(acc[e][f] - mx) * 0.0625f;
    }
}

// ---------------------------------------------------------------------------
// Kernel 2: chunk state contributions  S_c[m][dv] = sum_k phiK[k][m] * V[k][dv]
// grid (2 dv-tiles, 2 m-tiles, B*NC). 128x128 tile, blockDim (32,8),
// micro 16 rows (e*8+ty) x 4 cols (f*32+tx).
// ---------------------------------------------------------------------------
__global__ void __launch_bounds__(256) scontrib_kernel(const float* __restrict__ V)
{
    __shared__ float As[KT][128];   // phiK slice [k][m]
    __shared__ float Bs[KT][128];   // V slice    [k][dv]

    const int bc = blockIdx.z;
    const int b = bc / NCHUNK, c = bc % NCHUNK;
    const int m0  = blockIdx.y * 128;
    const int dv0 = blockIdx.x * 128;
    const size_t base = (size_t)b * SEQ + (size_t)c * CHUNK;
    const float* phiK = g_phiK + base * MM;
    const float* Vb   = V + base * DVV;
    float* Sout = g_S + (size_t)bc * MM * DVV;

    const int tx = threadIdx.x, ty = threadIdx.y;
    const int tid = ty * 32 + tx;

    float acc[16][4];
#pragma unroll
    for (int e = 0; e < 16; e++)
#pragma unroll
        for (int f = 0; f < 4; f++) acc[e][f] = 0.f;

    for (int k0 = 0; k0 < CHUNK; k0 += KT) {
#pragma unroll
        for (int e = 0; e < 8; e++) {
            int li = tid + e * 256;           // 2048 = 16*128
            int r = li >> 7, cc = li & 127;
            As[r][cc] = phiK[(size_t)(k0 + r) * MM + m0 + cc];
            Bs[r][cc] = Vb[(size_t)(k0 + r) * DVV + dv0 + cc];
        }
        __syncthreads();
#pragma unroll
        for (int k = 0; k < KT; k++) {
            float a[16], bb[4];
#pragma unroll
            for (int e = 0; e < 16; e++) a[e] = As[k][e * 8 + ty];
#pragma unroll
            for (int f = 0; f < 4; f++) bb[f] = Bs[k][f * 32 + tx];
#pragma unroll
            for (int e = 0; e < 16; e++)
#pragma unroll
                for (int f = 0; f < 4; f++) acc[e][f] = fmaf(a[e], bb[f], acc[e][f]);
        }
        __syncthreads();
    }
#pragma unroll
    for (int e = 0; e < 16; e++) {
        const size_t rowoff = (size_t)(m0 + e * 8 + ty) * DVV + dv0;
#pragma unroll
        for (int f = 0; f < 4; f++) Sout[rowoff + f * 32 + tx] = acc[e][f];
    }
}

// Kernel 2b: per-chunk column sums of phiK -> g_z[b][c][m]
__global__ void __launch_bounds__(256) zsum_kernel()
{
    const int bc = blockIdx.x;
    const int m = threadIdx.x;
    const size_t base = ((size_t)(bc / NCHUNK) * SEQ + (size_t)(bc % NCHUNK) * CHUNK) * MM;
    float s = 0.f;
#pragma unroll 8
    for (int k = 0; k < CHUNK; k++) s += g_phiK[base + (size_t)k * MM + m];
    g_z[(size_t)bc * MM + m] = s;
}

// Kernel 3a: in-place exclusive prefix over chunks for S (per b,m,dv lane)
__global__ void __launch_bounds__(256) prefixS_kernel()
{
    const size_t g = (size_t)blockIdx.x * 256 + threadIdx.x;   // B*M*DV lanes
    const size_t b = g / (MM * DVV);
    const size_t r = g % (MM * DVV);
    float* p = g_S + b * (size_t)NCHUNK * MM * DVV + r;
    float run = 0.f;
#pragma unroll 4
    for (int c = 0; c < NCHUNK; c++) {
        const size_t off = (size_t)c * MM * DVV;
        float v = p[off];
        p[off] = run;
        run += v;
    }
}

// Kernel 3b: in-place exclusive prefix over chunks for z
__global__ void __launch_bounds__(256) prefixz_kernel()
{
    const int g = blockIdx.x * 256 + threadIdx.x;   // B*M lanes
    const int b = g / MM, m = g % MM;
    float* p = g_z + (size_t)b * NCHUNK * MM + m;
    float run = 0.f;
#pragma unroll
    for (int c = 0; c < NCHUNK; c++) {
        float v = p[c * MM];
        p[c * MM] = run;
        run += v;
    }
}

// ---------------------------------------------------------------------------
// Kernel 4: per (b, chunk):
//   A = tril(Pq Pk^T)  (128x128, K=256), kept in smem
//   num = A @ V_chunk + Pq @ S_pre      (128x256)
//   den = rowsum(A) + Pq . z_pre        (128)
//   out = num / max(den, 1e-6)
// blockDim (32,8); 128-wide tiles, micro 16x4.
// ---------------------------------------------------------------------------
__global__ void __launch_bounds__(256) chunk_kernel(const float* __restrict__ V,
                                                    float* __restrict__ Out)
{
    extern __shared__ float sm[];
    float* As    = sm;                      // 128*128 = 16384
    float* Qt    = As + 128 * 128;          // KT*129  = 2064 (transposed phiQ tile)
    float* Kt    = Qt + KT * 129;           // KT*129  = 2064 (transposed phiK tile)
    float* Bs    = Kt + KT * 129;           // KT*128  = 2048 (V / S_pre tile)
    float* zs    = Bs + KT * 128;           // 256
    float* dsum  = zs + 256;                // 128 (den_intra)
    float* dpart = dsum + 128;              // 256 (den_inter partials)
    float* rden  = dpart + 256;             // 128 (1/den)

    const int bc = blockIdx.x;
    const int b = bc / NCHUNK, c = bc % NCHUNK;
    const size_t base = (size_t)b * SEQ + (size_t)c * CHUNK;
    const float* phiQ = g_phiQ + base * MM;
    const float* phiK = g_phiK + base * MM;
    const float* Vb   = V + base * DVV;
    const float* Spre = g_S + (size_t)bc * MM * DVV;
    const float* zpre = g_z + (size_t)bc * MM;

    const int tx = threadIdx.x, ty = threadIdx.y;
    const int tid = ty * 32 + tx;

    // ---------------- Phase A: A = Pq Pk^T over K=256 (m) ----------------
    float acc[16][4];
#pragma unroll
    for (int e = 0; e < 16; e++)
#pragma unroll
        for (int f = 0; f < 4; f++) acc[e][f] = 0.f;

    for (int m0 = 0; m0 < MM; m0 += KT) {
#pragma unroll
        for (int e = 0; e < 8; e++) {
            int li = tid + e * 256;            // 2048 = 128*16
            int r = li >> 4, cc = li & 15;
            Qt[cc * 129 + r] = phiQ[(size_t)r * MM + m0 + cc];
            Kt[cc * 129 + r] = phiK[(size_t)r * MM + m0 + cc];
        }
        __syncthreads();
#pragma unroll
        for (int k = 0; k < KT; k++) {
            float a[16], bb[4];
#pragma unroll
            for (int e = 0; e < 16; e++) a[e] = Qt[k * 129 + e * 8 + ty];
#pragma unroll
            for (int f = 0; f < 4; f++) bb[f] = Kt[k * 129 + f * 32 + tx];
#pragma unroll
            for (int e = 0; e < 16; e++)
#pragma unroll
                for (int f = 0; f < 4; f++) acc[e][f] = fmaf(a[e], bb[f], acc[e][f]);
        }
        __syncthreads();
    }

    // mask + write A to smem + den_intra (rowsum of tril)
#pragma unroll
    for (int e = 0; e < 16; e++) {
        const int row = e * 8 + ty;
        float dp = 0.f;
#pragma unroll
        for (int f = 0; f < 4; f++) {
            const int col = f * 32 + tx;
            const float v = (col <= row) ? acc[e][f] : 0.f;
            As[row * 128 + col] = v;
            dp += v;
        }
#pragma unroll
        for (int o = 16; o > 0; o >>= 1) dp += __shfl_xor_sync(0xffffffffu, dp, o);
        if (tx == 0) dsum[row] = dp;
    }
    zs[tid] = zpre[tid];
    __syncthreads();

    // den_inter: 2 threads per row, each half of the 256 m's
    {
        const int row = tid >> 1;
        const int half = tid & 1;
        const float* q = phiQ + (size_t)row * MM + half * 128;
        const float* z = zs + half * 128;
        float p = 0.f;
#pragma unroll 8
        for (int m = 0; m < 128; m++) p = fmaf(q[m], z[m], p);
        dpart[tid] = p;
    }
    __syncthreads();
    if (tid < 128) {
        const float d = dsum[tid] + dpart[2 * tid] + dpart[2 * tid + 1];
        rden[tid] = 1.f / fmaxf(d, 1e-6f);
    }
    __syncthreads();

    // ---------------- Phase B: num = A@V + Pq@Spre, two 128-wide dv halves
    for (int dvh = 0; dvh < 2; dvh++) {
        const int dv0 = dvh * 128;
        float acc2[16][4];
#pragma unroll
        for (int e = 0; e < 16; e++)
#pragma unroll
            for (int f = 0; f < 4; f++) acc2[e][f] = 0.f;

        // intra: K = 128 (j), A from smem (broadcast reads), V tiles in Bs
        for (int j0 = 0; j0 < CHUNK; j0 += KT) {
#pragma unroll
            for (int e = 0; e < 8; e++) {
                int li = tid + e * 256;        // 2048 = 16*128
                int r = li >> 7, cc = li & 127;
                Bs[r * 128 + cc] = Vb[(size_t)(j0 + r) * DVV + dv0 + cc];
            }
            __syncthreads();
#pragma unroll
            for (int k = 0; k < KT; k++) {
                float a[16], bb[4];
#pragma unroll
                for (int e = 0; e < 16; e++) a[e] = As[(e * 8 + ty) * 128 + j0 + k];
#pragma unroll
                for (int f = 0; f < 4; f++) bb[f] = Bs[k * 128 + f * 32 + tx];
#pragma unroll
                for (int e = 0; e < 16; e++)
#pragma unroll
                    for (int f = 0; f < 4; f++) acc2[e][f] = fmaf(a[e], bb[f], acc2[e][f]);
            }
            __syncthreads();
        }

        // inter: K = 256 (m), Pq transposed tiles in Qt, S_pre tiles in Bs
        for (int m0 = 0; m0 < MM; m0 += KT) {
#pragma unroll
            for (int e = 0; e < 8; e++) {
                int li = tid + e * 256;
                {   // Qt: 128 rows x 16 m, transposed
                    int r = li >> 4, cc = li & 15;
                    Qt[cc * 129 + r] = phiQ[(size_t)r * MM + m0 + cc];
                }
                {   // Bs: 16 m-rows x 128 dv
                    int r = li >> 7, cc = li & 127;
                    Bs[r * 128 + cc] = Spre[(size_t)(m0 + r) * DVV + dv0 + cc];
                }
            }
            __syncthreads();
#pragma unroll
            for (int k = 0; k < KT; k++) {
                float a[16], bb[4];
#pragma unroll
                for (int e = 0; e < 16; e++) a[e] = Qt[k * 129 + e * 8 + ty];
#pragma unroll
                for (int f = 0; f < 4; f++) bb[f] = Bs[k * 128 + f * 32 + tx];
#pragma unroll
                for (int e = 0; e < 16; e++)
#pragma unroll
                    for (int f = 0; f < 4; f++) acc2[e][f] = fmaf(a[e], bb[f], acc2[e][f]);
            }
            __syncthreads();
        }

        // epilogue
#pragma unroll
        for (int e = 0; e < 16; e++) {
            const int row = e * 8 + ty;
            const float r = rden[row];
            const size_t rowoff = (base + row) * DVV + dv0;
#pragma unroll
            for (int f = 0; f < 4; f++)
                Out[rowoff + f * 32 + tx] = acc2[e][f] * r;
        }
    }
}

// ---------------------------------------------------------------------------
extern "C" void kernel_launch(void* const* d_in, const int* in_sizes, int n_in,
                              void* d_out, int out_size)
{
    (void)in_sizes; (void)n_in; (void)out_size;
    const float* Q   = (const float*)d_in[0];
    const float* Kin = (const float*)d_in[1];
    const float* V   = (const float*)d_in[2];
    const float* W   = (const float*)d_in[3];
    // d_in[4] is the causal flag; this dataset is always causal=1.
    float* Out = (float*)d_out;

    dim3 blk(32, 8);

    // 1) phi for Q and K
    phi_kernel<<<dim3(BATCH * SEQ / 64, 2), blk>>>(Q, Kin, W);

    // 2) chunk state contributions + chunk z sums
    scontrib_kernel<<<dim3(2, 2, BATCH * NCHUNK), blk>>>(V);
    zsum_kernel<<<BATCH * NCHUNK, 256>>>();

    // 3) exclusive prefixes across chunks
    prefixS_kernel<<<(BATCH * MM * DVV) / 256, 256>>>();
    prefixz_kernel<<<(BATCH * MM) / 256, 256>>>();

    // 4) main per-chunk kernel
    const int smem_bytes = (128 * 128 + 2 * KT * 129 + KT * 128 + 256 + 128 + 256 + 128) * 4;
    cudaFuncSetAttribute(chunk_kernel, cudaFuncAttributeMaxDynamicSharedMemorySize, smem_bytes);
    chunk_kernel<<<BATCH * NCHUNK, blk, smem_bytes>>>(V, Out);
}

// round 3
// speedup vs baseline: 1.5153x; 1.5153x over previous
#include <cuda_runtime.h>
#include <cuda_bf16.h>

// Performer (FAVOR+) causal attention, chunked linear-attention decomposition.
// B=8, N=4096, D=256, M=256, DV=256. Chunk C=128, NC=32.
//
// out = (tril(Pq Pk^T) V + Pq S_pre) / (rowsum(tril(Pq Pk^T)) + Pq z_pre)
// phi(x) = exp(proj - rowmax(proj))/16  (|x|^2 term cancels in the shift)
//
// All GEMM inner loops use packed fma.rn.f32x2 (FFMA2) for 2x fp32 issue rate.

#define BATCH 8
#define SEQ   4096
#define DD    256
#define MM    256
#define DVV   256
#define CHUNK 128
#define NCHUNK (SEQ / CHUNK)   // 32
#define KT    16

typedef unsigned long long u64;

__device__ __forceinline__ void ffma2(u64& d, u64 a, u64 b) {
    asm("fma.rn.f32x2 %0, %1, %2, %0;" : "+l"(d) : "l"(a), "l"(b));
}
__device__ __forceinline__ u64 pack2(float lo, float hi) {
    u64 r; asm("mov.b64 %0, {%1, %2};" : "=l"(r) : "f"(lo), "f"(hi)); return r;
}
__device__ __forceinline__ void unpack2(float& lo, float& hi, u64 v) {
    asm("mov.b64 {%0, %1}, %2;" : "=f"(lo), "=f"(hi) : "l"(v));
}
__device__ __forceinline__ void add2(u64& d, u64 a, u64 b) {
    asm("add.rn.f32x2 %0, %1, %2;" : "=l"(d) : "l"(a), "l"(b));
}
__device__ __forceinline__ void mul2(u64& d, u64 a, u64 b) {
    asm("mul.rn.f32x2 %0, %1, %2;" : "=l"(d) : "l"(a), "l"(b));
}

// Scratch (device globals; no allocation allowed)
__device__ float g_phiQ[BATCH * SEQ * MM];
__device__ float g_phiK[BATCH * SEQ * MM];
__device__ float g_S[BATCH * NCHUNK * MM * DVV];
__device__ float g_z[BATCH * NCHUNK * MM];

// ---------------------------------------------------------------------------
// Kernel 1: phi = exp(X @ W^T - rowmax)/16.  64 rows x 256 cols per CTA.
// Micro: row-pairs via LDS.64 broadcast (rows 2u,2u+1; u=e*8+ty, e<4),
// cols f*32+tx (f<8, b duplicated).  32 FFMA2 per k.
// ---------------------------------------------------------------------------
__global__ void __launch_bounds__(256) phi_kernel(const float* __restrict__ Q,
                                                  const float* __restrict__ Kin,
                                                  const float* __restrict__ W)
{
    __shared__ __align__(16) float Xs[KT][66];    // [k][row], padded even
    __shared__ __align__(16) float Ws[KT][257];   // [k][m]

    const float* X  = (blockIdx.y == 0) ? Q : Kin;
    float*      Phi = (blockIdx.y == 0) ? g_phiQ : g_phiK;

    const int row0 = blockIdx.x * 64;
    const int tx = threadIdx.x, ty = threadIdx.y;
    const int tid = ty * 32 + tx;

    u64 acc[4][8];
#pragma unroll
    for (int e = 0; e < 4; e++)
#pragma unroll
        for (int f = 0; f < 8; f++) acc[e][f] = 0ull;

    for (int d0 = 0; d0 < DD; d0 += KT) {
#pragma unroll
        for (int e = 0; e < 4; e++) {
            int li = tid + e * 256;            // 1024 = 64*16
            int r = li >> 4, c = li & 15;
            Xs[c][r] = X[(size_t)(row0 + r) * DD + d0 + c];
        }
#pragma unroll
        for (int e = 0; e < 16; e++) {
            int li = tid + e * 256;            // 4096 = 256*16
            int r = li >> 4, c = li & 15;
            Ws[c][r] = W[(size_t)r * DD + d0 + c];
        }
        __syncthreads();
#pragma unroll
        for (int k = 0; k < KT; k++) {
            u64 a2[4], b2[8];
#pragma unroll
            for (int e = 0; e < 4; e++)
                a2[e] = *reinterpret_cast<const u64*>(&Xs[k][2 * (e * 8 + ty)]);
#pragma unroll
            for (int f = 0; f < 8; f++) {
                float b = Ws[k][f * 32 + tx];
                b2[f] = pack2(b, b);
            }
#pragma unroll
            for (int e = 0; e < 4; e++)
#pragma unroll
                for (int f = 0; f < 8; f++) ffma2(acc[e][f], a2[e], b2[f]);
        }
        __syncthreads();
    }

#pragma unroll
    for (int e = 0; e < 4; e++) {
        const int u = e * 8 + ty;
        float lo[8], hi[8];
#pragma unroll
        for (int f = 0; f < 8; f++) unpack2(lo[f], hi[f], acc[e][f]);
        float mlo = lo[0], mhi = hi[0];
#pragma unroll
        for (int f = 1; f < 8; f++) { mlo = fmaxf(mlo, lo[f]); mhi = fmaxf(mhi, hi[f]); }
#pragma unroll
        for (int o = 16; o > 0; o >>= 1) {
            mlo = fmaxf(mlo, __shfl_xor_sync(0xffffffffu, mlo, o));
            mhi = fmaxf(mhi, __shfl_xor_sync(0xffffffffu, mhi, o));
        }
        const size_t ro0 = (size_t)(row0 + 2 * u) * MM;
        const size_t ro1 = ro0 + MM;
#pragma unroll
        for (int f = 0; f < 8; f++) {
            Phi[ro0 + f * 32 + tx] = __expf(lo[f] - mlo) * 0.0625f;
            Phi[ro1 + f * 32 + tx] = __expf(hi[f] - mhi) * 0.0625f;
        }
    }
}

// ---------------------------------------------------------------------------
// Kernel 2: S_c[m][dv] = sum_k phiK[k][m] * V[k][dv]; fused z[m] = sum_k phiK[k][m]
// Grid (2 dv, 2 m, B*NC).  Micro: row-pairs on m via LDS.64, cols f*32+tx.
// ---------------------------------------------------------------------------
__global__ void __launch_bounds__(256) scontrib_kernel(const float* __restrict__ V)
{
    __shared__ __align__(16) float As[KT][128];   // phiK [k][m]
    __shared__ __align__(16) float Bs[KT][128];   // V    [k][dv]
    __shared__ float zp[256];

    const int bc = blockIdx.z;
    const int b = bc / NCHUNK, c = bc % NCHUNK;
    const int m0  = blockIdx.y * 128;
    const int dv0 = blockIdx.x * 128;
    const size_t base = (size_t)b * SEQ + (size_t)c * CHUNK;
    const float* phiK = g_phiK + base * MM;
    const float* Vb   = V + base * DVV;
    float* Sout = g_S + (size_t)bc * MM * DVV;
    const bool do_z = (blockIdx.x == 0);

    const int tx = threadIdx.x, ty = threadIdx.y;
    const int tid = ty * 32 + tx;

    u64 acc[8][4];
#pragma unroll
    for (int e = 0; e < 8; e++)
#pragma unroll
        for (int f = 0; f < 4; f++) acc[e][f] = 0ull;
    float zacc = 0.f;

    for (int k0 = 0; k0 < CHUNK; k0 += KT) {
#pragma unroll
        for (int e = 0; e < 8; e++) {
            int li = tid + e * 256;           // 2048 = 16*128
            int r = li >> 7, cc = li & 127;
            float av = phiK[(size_t)(k0 + r) * MM + m0 + cc];
            As[r][cc] = av;
            if (do_z) zacc += av;
            Bs[r][cc] = Vb[(size_t)(k0 + r) * DVV + dv0 + cc];
        }
        __syncthreads();
#pragma unroll
        for (int k = 0; k < KT; k++) {
            u64 a2[8], b2[4];
#pragma unroll
            for (int e = 0; e < 8; e++)
                a2[e] = *reinterpret_cast<const u64*>(&As[k][2 * (e * 8 + ty)]);
#pragma unroll
            for (int f = 0; f < 4; f++) {
                float bv = Bs[k][f * 32 + tx];
                b2[f] = pack2(bv, bv);
            }
#pragma unroll
            for (int e = 0; e < 8; e++)
#pragma unroll
                for (int f = 0; f < 4; f++) ffma2(acc[e][f], a2[e], b2[f]);
        }
        __syncthreads();
    }
#pragma unroll
    for (int e = 0; e < 8; e++) {
        const int u = e * 8 + ty;
        const size_t r0 = (size_t)(m0 + 2 * u) * DVV + dv0;
        const size_t r1 = r0 + DVV;
#pragma unroll
        for (int f = 0; f < 4; f++) {
            float lo, hi; unpack2(lo, hi, acc[e][f]);
            Sout[r0 + f * 32 + tx] = lo;
            Sout[r1 + f * 32 + tx] = hi;
        }
    }
    if (do_z) {
        zp[tid] = zacc;
        __syncthreads();
        if (tid < 128) g_z[(size_t)bc * MM + m0 + tid] = zp[tid] + zp[tid + 128];
    }
}

// Kernel 3a: exclusive prefix over chunks for S, MLP=32 (batch loads).
__global__ void __launch_bounds__(256) prefixS_kernel()
{
    const size_t g = (size_t)blockIdx.x * 256 + threadIdx.x;   // B*M*DV lanes
    const size_t b = g >> 16;              // / 65536
    const size_t r = g & 65535;
    float* p = g_S + b * (size_t)NCHUNK * MM * DVV + r;
    float v[NCHUNK];
#pragma unroll
    for (int c = 0; c < NCHUNK; c++) v[c] = p[(size_t)c * MM * DVV];
    float run = 0.f;
#pragma unroll
    for (int c = 0; c < NCHUNK; c++) { float t = v[c]; v[c] = run; run += t; }
#pragma unroll
    for (int c = 0; c < NCHUNK; c++) p[(size_t)c * MM * DVV] = v[c];
}

// Kernel 3b: exclusive prefix over chunks for z.
__global__ void __launch_bounds__(256) prefixz_kernel()
{
    const int g = blockIdx.x * 256 + threadIdx.x;   // B*M lanes
    const int b = g / MM, m = g % MM;
    float* p = g_z + (size_t)b * NCHUNK * MM + m;
    float v[NCHUNK];
#pragma unroll
    for (int c = 0; c < NCHUNK; c++) v[c] = p[c * MM];
    float run = 0.f;
#pragma unroll
    for (int c = 0; c < NCHUNK; c++) { float t = v[c]; v[c] = run; run += t; }
#pragma unroll
    for (int c = 0; c < NCHUNK; c++) p[c * MM] = v[c];
}

// ---------------------------------------------------------------------------
// Kernel 4: inter GEMM  Out_raw[t][dv] = sum_m phiQ[t][m] * Spre[chunk(t)][m][dv]
// Grid (2 dv, B*NC).  Row-pairs via LDS.64 on transposed Qt, cols f*32+tx.
// ---------------------------------------------------------------------------
__global__ void __launch_bounds__(256) inter_kernel(float* __restrict__ Out)
{
    __shared__ __align__(16) float Qt[KT * 130];   // [k][row], stride 130 (even)
    __shared__ __align__(16) float Bs[KT * 128];   // Spre [k(m)][dv]

    const int bc = blockIdx.y;
    const int dv0 = blockIdx.x * 128;
    const size_t base = ((size_t)(bc / NCHUNK) * SEQ + (size_t)(bc % NCHUNK) * CHUNK);
    const float* phiQ = g_phiQ + base * MM;
    const float* Spre = g_S + (size_t)bc * MM * DVV;

    const int tx = threadIdx.x, ty = threadIdx.y;
    const int tid = ty * 32 + tx;

    u64 acc[8][4];
#pragma unroll
    for (int e = 0; e < 8; e++)
#pragma unroll
        for (int f = 0; f < 4; f++) acc[e][f] = 0ull;

    for (int m0 = 0; m0 < MM; m0 += KT) {
#pragma unroll
        for (int e = 0; e < 8; e++) {
            int li = tid + e * 256;            // 2048
            {   // Qt: 128 rows x 16 m, transposed
                int r = li >> 4, c = li & 15;
                Qt[c * 130 + r] = phiQ[(size_t)r * MM + m0 + c];
            }
            {   // Bs: 16 m-rows x 128 dv
                int r = li >> 7, cc = li & 127;
                Bs[r * 128 + cc] = Spre[(size_t)(m0 + r) * DVV + dv0 + cc];
            }
        }
        __syncthreads();
#pragma unroll
        for (int k = 0; k < KT; k++) {
            u64 a2[8], b2[4];
#pragma unroll
            for (int e = 0; e < 8; e++)
                a2[e] = *reinterpret_cast<const u64*>(&Qt[k * 130 + 2 * (e * 8 + ty)]);
#pragma unroll
            for (int f = 0; f < 4; f++) {
                float bv = Bs[k * 128 + f * 32 + tx];
                b2[f] = pack2(bv, bv);
            }
#pragma unroll
            for (int e = 0; e < 8; e++)
#pragma unroll
                for (int f = 0; f < 4; f++) ffma2(acc[e][f], a2[e], b2[f]);
        }
        __syncthreads();
    }
#pragma unroll
    for (int e = 0; e < 8; e++) {
        const int u = e * 8 + ty;
        const size_t r0 = (base + 2 * u) * DVV + dv0;
        const size_t r1 = r0 + DVV;
#pragma unroll
        for (int f = 0; f < 4; f++) {
            float lo, hi; unpack2(lo, hi, acc[e][f]);
            Out[r0 + f * 32 + tx] = lo;
            Out[r1 + f * 32 + tx] = hi;
        }
    }
}

// ---------------------------------------------------------------------------
// Kernel 5: per (b, chunk):
//   A = tril(Pq Pk^T)  (128x128, K=256) kept in smem; den_inter fused in
//   Phase A (one extra FFMA2 per k against z_pre).
//   Phase B: intra = A @ V, add Out_raw (inter), normalize by den.
// ---------------------------------------------------------------------------
__global__ void __launch_bounds__(256) chunk_kernel(const float* __restrict__ V,
                                                    float* __restrict__ Out)
{
    extern __shared__ __align__(16) float sm[];
    float* As   = sm;                   // 128*128 = 16384
    float* Qt   = As + 128 * 128;       // KT*130  = 2080
    float* Kt   = Qt + KT * 130;        // KT*130  = 2080
    float* Bs   = Kt + KT * 130;        // KT*128  = 2048
    float* zs   = Bs + KT * 128;        // 256
    float* dsum = zs + 256;             // 128
    float* dins = dsum + 128;           // 128
    float* rden = dins + 128;           // 128

    const int bc = blockIdx.x;
    const size_t base = ((size_t)(bc / NCHUNK) * SEQ + (size_t)(bc % NCHUNK) * CHUNK);
    const float* phiQ = g_phiQ + base * MM;
    const float* phiK = g_phiK + base * MM;
    const float* Vb   = V + base * DVV;
    const float* zpre = g_z + (size_t)bc * MM;

    const int tx = threadIdx.x, ty = threadIdx.y;
    const int tid = ty * 32 + tx;

    zs[tid] = zpre[tid];

    // ---- Phase A: A = Pq Pk^T over K=256, + den_inter ----
    u64 acc[8][4], dint[8];
#pragma unroll
    for (int e = 0; e < 8; e++) {
        dint[e] = 0ull;
#pragma unroll
        for (int f = 0; f < 4; f++) acc[e][f] = 0ull;
    }

    for (int m0 = 0; m0 < MM; m0 += KT) {
#pragma unroll
        for (int e = 0; e < 8; e++) {
            int li = tid + e * 256;
            int r = li >> 4, c = li & 15;
            Qt[c * 130 + r] = phiQ[(size_t)r * MM + m0 + c];
            Kt[c * 130 + r] = phiK[(size_t)r * MM + m0 + c];
        }
        __syncthreads();
#pragma unroll
        for (int k = 0; k < KT; k++) {
            const float zz = zs[m0 + k];
            const u64 z2 = pack2(zz, zz);
            u64 a2[8], b2[4];
#pragma unroll
            for (int e = 0; e < 8; e++)
                a2[e] = *reinterpret_cast<const u64*>(&Qt[k * 130 + 2 * (e * 8 + ty)]);
#pragma unroll
            for (int f = 0; f < 4; f++) {
                float bv = Kt[k * 130 + f * 32 + tx];
                b2[f] = pack2(bv, bv);
            }
#pragma unroll
            for (int e = 0; e < 8; e++) {
                ffma2(dint[e], a2[e], z2);
#pragma unroll
                for (int f = 0; f < 4; f++) ffma2(acc[e][f], a2[e], b2[f]);
            }
        }
        __syncthreads();
    }

    // mask tril, stash A, rowsum -> dsum; den_inter -> dins
#pragma unroll
    for (int e = 0; e < 8; e++) {
        const int r0 = 2 * (e * 8 + ty);
        float dplo = 0.f, dphi = 0.f;
#pragma unroll
        for (int f = 0; f < 4; f++) {
            const int col = f * 32 + tx;
            float lo, hi; unpack2(lo, hi, acc[e][f]);
            lo = (col <= r0)     ? lo : 0.f;
            hi = (col <= r0 + 1) ? hi : 0.f;
            As[r0 * 128 + col] = lo;
            As[(r0 + 1) * 128 + col] = hi;
            dplo += lo; dphi += hi;
        }
#pragma unroll
        for (int o = 16; o > 0; o >>= 1) {
            dplo += __shfl_xor_sync(0xffffffffu, dplo, o);
            dphi += __shfl_xor_sync(0xffffffffu, dphi, o);
        }
        if (tx == 0) {
            dsum[r0] = dplo; dsum[r0 + 1] = dphi;
            float il, ih; unpack2(il, ih, dint[e]);
            dins[r0] = il; dins[r0 + 1] = ih;
        }
    }
    __syncthreads();
    if (tid < 128) rden[tid] = 1.f / fmaxf(dsum[tid] + dins[tid], 1e-6f);
    __syncthreads();

    // ---- Phase B: intra = A @ V (col-pairs), add inter, normalize ----
    for (int dvh = 0; dvh < 2; dvh++) {
        const int dv0 = dvh * 128;
        u64 acc2[16][2];
#pragma unroll
        for (int e = 0; e < 16; e++)
#pragma unroll
            for (int f = 0; f < 2; f++) acc2[e][f] = 0ull;

        for (int j0 = 0; j0 < CHUNK; j0 += KT) {
#pragma unroll
            for (int e = 0; e < 8; e++) {
                int li = tid + e * 256;
                int r = li >> 7, cc = li & 127;
                Bs[r * 128 + cc] = Vb[(size_t)(j0 + r) * DVV + dv0 + cc];
            }
            __syncthreads();
#pragma unroll
            for (int k = 0; k < KT; k++) {
                u64 b2[2];
#pragma unroll
                for (int f = 0; f < 2; f++)
                    b2[f] = *reinterpret_cast<const u64*>(&Bs[k * 128 + f * 64 + tx * 2]);
#pragma unroll
                for (int e = 0; e < 16; e++) {
                    float av = As[(e * 8 + ty) * 128 + j0 + k];
                    u64 a2 = pack2(av, av);
#pragma unroll
                    for (int f = 0; f < 2; f++) ffma2(acc2[e][f], a2, b2[f]);
                }
            }
            __syncthreads();
        }

#pragma unroll
        for (int e = 0; e < 16; e++) {
            const int row = e * 8 + ty;
            const float r = rden[row];
            const u64 r2 = pack2(r, r);
            const size_t rowoff = (base + row) * DVV + dv0;
#pragma unroll
            for (int f = 0; f < 2; f++) {
                u64* po = reinterpret_cast<u64*>(&Out[rowoff + f * 64 + tx * 2]);
                u64 o = *po, s;
                add2(s, o, acc2[e][f]);
                mul2(s, s, r2);
                *po = s;
            }
        }
    }
}

// ---------------------------------------------------------------------------
extern "C" void kernel_launch(void* const* d_in, const int* in_sizes, int n_in,
                              void* d_out, int out_size)
{
    (void)in_sizes; (void)n_in; (void)out_size;
    const float* Q   = (const float*)d_in[0];
    const float* Kin = (const float*)d_in[1];
    const float* V   = (const float*)d_in[2];
    const float* W   = (const float*)d_in[3];
    float* Out = (float*)d_out;

    dim3 blk(32, 8);

    phi_kernel<<<dim3(BATCH * SEQ / 64, 2), blk>>>(Q, Kin, W);
    scontrib_kernel<<<dim3(2, 2, BATCH * NCHUNK), blk>>>(V);
    prefixS_kernel<<<(BATCH * MM * DVV) / 256, 256>>>();
    prefixz_kernel<<<(BATCH * MM) / 256, 256>>>();
    inter_kernel<<<dim3(2, BATCH * NCHUNK), blk>>>(Out);

    const int smem_bytes = (128 * 128 + 2 * KT * 130 + KT * 128 + 256 + 3 * 128) * 4;
    cudaFuncSetAttribute(chunk_kernel, cudaFuncAttributeMaxDynamicSharedMemorySize, smem_bytes);
    chunk_kernel<<<BATCH * NCHUNK, blk, smem_bytes>>>(V, Out);
}

// round 6
// speedup vs baseline: 2.4518x; 1.6180x over previous
#include <cuda_runtime.h>
#include <cstdint>

// Performer (FAVOR+) causal attention — mma.sync (HMMA) tf32 implementation.
// (tcgen05 unavailable: harness builds compute_103 PTX, no 'a' features.)
// B=8, N=4096, D=256, M=256, DV=256. Chunk C=128, NC=32.
//
// out = (tril(Pq Pk^T) V + Pq S_pre) / (rowsum(tril(Pq Pk^T)) + Pq z_pre)
// phi(x) = exp(proj - rowmax(proj))/16      (|x|^2 cancels in the shift)
//
// phi projection uses 3xTF32 (hi/lo split). All downstream MMA operands are
// exact tf32 values so num/den weight sets match and rounding cancels.

#define BATCH 8
#define SEQ   4096
#define DD    256
#define MM    256
#define DVV   256
#define CHUNK 128
#define NCHUNK 32

__device__ float g_phiQ[BATCH * SEQ * MM];
__device__ float g_phiK[BATCH * SEQ * MM];
__device__ float g_V32 [BATCH * SEQ * DVV];
__device__ float g_S   [BATCH * NCHUNK * MM * DVV];   // [bc][m][dv]
__device__ float g_z   [BATCH * NCHUNK * MM];
__device__ float g_den [BATCH * NCHUNK * CHUNK];      // den_inter per row

__device__ __forceinline__ uint32_t su32(const void* p) {
    uint32_t a;
    asm("{ .reg .u64 t; cvta.to.shared.u64 t, %1; cvt.u32.u64 %0, t; }" : "=r"(a) : "l"(p));
    return a;
}
__device__ __forceinline__ void cpa(uint32_t d, const float* s) {
    asm volatile("cp.async.cg.shared.global [%0], [%1], 16;" :: "r"(d), "l"(s));
}
#define CP_COMMIT() asm volatile("cp.async.commit_group;" ::: "memory")
#define CP_WAIT1()  asm volatile("cp.async.wait_group 1;" ::: "memory")
#define CP_WAIT0()  asm volatile("cp.async.wait_group 0;" ::: "memory")

__device__ __forceinline__ float tf32r(float x) {
    uint32_t h; asm("cvt.rna.tf32.f32 %0, %1;" : "=r"(h) : "f"(x));
    return __uint_as_float(h);
}
__device__ __forceinline__ void mma8(float* c, const uint32_t* a, const uint32_t* b) {
    asm volatile(
        "mma.sync.aligned.m16n8k8.row.col.f32.tf32.tf32.f32 "
        "{%0,%1,%2,%3},{%4,%5,%6,%7},{%8,%9},{%0,%1,%2,%3};"
        : "+f"(c[0]), "+f"(c[1]), "+f"(c[2]), "+f"(c[3])
        : "r"(a[0]), "r"(a[1]), "r"(a[2]), "r"(a[3]), "r"(b[0]), "r"(b[1]));
}
__device__ __forceinline__ uint32_t fb(float x) { return __float_as_uint(x); }

// ---------------------------------------------------------------------------
// Kernel 1: phi = exp(X @ W^T - rowmax)/16, 3xTF32.
// grid 512 (bid<256 -> Q else K_in). CTA 128 rows x 256 cols, K=256.
// Warps 4x2 (wm,wn); warp tile 32x128. smem [row][k16] stride 20.
// ---------------------------------------------------------------------------
#define PHI_SMEM ((2*2560*2 + 2*5120*2 + 256) * 4)

__global__ void __launch_bounds__(256) phi_mma(const float* __restrict__ Q,
                                               const float* __restrict__ Kin,
                                               const float* __restrict__ W)
{
    extern __shared__ float sm[];
    float* Xh = sm;                 // 2 bufs * 128*20
    float* Xl = Xh + 5120;
    float* Wh = Xl + 5120;          // 2 bufs * 256*20
    float* Wl = Wh + 10240;
    float* rmax = Wl + 10240;       // 256

    const int tid = threadIdx.x;
    const int lane = tid & 31, w = tid >> 5;
    const int gid = lane >> 2, tig = lane & 3;
    const int wm = w >> 1, wn = w & 1;

    const int bid = blockIdx.x;
    const float* X = (bid < 256) ? Q : Kin;
    float* Phi = (bid < 256) ? g_phiQ : g_phiK;
    const size_t row0 = (size_t)(bid & 255) * 128;

    float acc[2][16][4];
#pragma unroll
    for (int mt = 0; mt < 2; mt++)
#pragma unroll
        for (int nt = 0; nt < 16; nt++)
#pragma unroll
            for (int i = 0; i < 4; i++) acc[mt][nt][i] = 0.f;

    const int xr = tid >> 1, xc = (tid & 1) * 8;
    const float* xsrc = X + (row0 + xr) * DD + xc;
    const float* wsrc = W + (size_t)tid * DD;

    float4 rx0, rx1, rw0, rw1, rw2, rw3;

#define PHI_LD(st) { \
    const float* p = xsrc + (st) * 16; \
    rx0 = *(const float4*)p; rx1 = *(const float4*)(p + 4); \
    const float* q = wsrc + (st) * 16; \
    rw0 = *(const float4*)q;       rw1 = *(const float4*)(q + 4); \
    rw2 = *(const float4*)(q + 8); rw3 = *(const float4*)(q + 12); }

#define SPL(v, ph, pl) { float _h = tf32r(v); (ph) = _h; (pl) = (v) - _h; }

#define PHI_ST(bf) { \
    float* dxh = Xh + (bf) * 2560 + xr * 20 + xc; \
    float* dxl = Xl + (bf) * 2560 + xr * 20 + xc; \
    SPL(rx0.x, dxh[0], dxl[0]); SPL(rx0.y, dxh[1], dxl[1]); \
    SPL(rx0.z, dxh[2], dxl[2]); SPL(rx0.w, dxh[3], dxl[3]); \
    SPL(rx1.x, dxh[4], dxl[4]); SPL(rx1.y, dxh[5], dxl[5]); \
    SPL(rx1.z, dxh[6], dxl[6]); SPL(rx1.w, dxh[7], dxl[7]); \
    float* dwh = Wh + (bf) * 5120 + tid * 20; \
    float* dwl = Wl + (bf) * 5120 + tid * 20; \
    SPL(rw0.x, dwh[0],  dwl[0]);  SPL(rw0.y, dwh[1],  dwl[1]); \
    SPL(rw0.z, dwh[2],  dwl[2]);  SPL(rw0.w, dwh[3],  dwl[3]); \
    SPL(rw1.x, dwh[4],  dwl[4]);  SPL(rw1.y, dwh[5],  dwl[5]); \
    SPL(rw1.z, dwh[6],  dwl[6]);  SPL(rw1.w, dwh[7],  dwl[7]); \
    SPL(rw2.x, dwh[8],  dwl[8]);  SPL(rw2.y, dwh[9],  dwl[9]); \
    SPL(rw2.z, dwh[10], dwl[10]); SPL(rw2.w, dwh[11], dwl[11]); \
    SPL(rw3.x, dwh[12], dwl[12]); SPL(rw3.y, dwh[13], dwl[13]); \
    SPL(rw3.z, dwh[14], dwl[14]); SPL(rw3.w, dwh[15], dwl[15]); }

    PHI_LD(0); PHI_ST(0);
    __syncthreads();

#pragma unroll 1
    for (int st = 0; st < 16; st++) {
        const int buf = st & 1;
        if (st < 15) PHI_LD(st + 1);

        const float* xh = Xh + buf * 2560;
        const float* xl = Xl + buf * 2560;
        const float* wh = Wh + buf * 5120;
        const float* wl = Wl + buf * 5120;
#pragma unroll
        for (int k8 = 0; k8 < 16; k8 += 8) {
            uint32_t ah[2][4], al[2][4];
#pragma unroll
            for (int mt = 0; mt < 2; mt++) {
                const int rb = wm * 32 + mt * 16;
                ah[mt][0] = fb(xh[(rb + gid) * 20 + k8 + tig]);
                ah[mt][1] = fb(xh[(rb + gid + 8) * 20 + k8 + tig]);
                ah[mt][2] = fb(xh[(rb + gid) * 20 + k8 + tig + 4]);
                ah[mt][3] = fb(xh[(rb + gid + 8) * 20 + k8 + tig + 4]);
                al[mt][0] = fb(xl[(rb + gid) * 20 + k8 + tig]);
                al[mt][1] = fb(xl[(rb + gid + 8) * 20 + k8 + tig]);
                al[mt][2] = fb(xl[(rb + gid) * 20 + k8 + tig + 4]);
                al[mt][3] = fb(xl[(rb + gid + 8) * 20 + k8 + tig + 4]);
            }
#pragma unroll
            for (int nt = 0; nt < 16; nt++) {
                const int nb = wn * 128 + nt * 8;
                uint32_t bh[2] = { fb(wh[(nb + gid) * 20 + k8 + tig]),
                                   fb(wh[(nb + gid) * 20 + k8 + tig + 4]) };
                uint32_t bl[2] = { fb(wl[(nb + gid) * 20 + k8 + tig]),
                                   fb(wl[(nb + gid) * 20 + k8 + tig + 4]) };
                mma8(acc[0][nt], ah[0], bh);
                mma8(acc[1][nt], ah[1], bh);
                mma8(acc[0][nt], ah[0], bl);
                mma8(acc[1][nt], ah[1], bl);
                mma8(acc[0][nt], al[0], bh);
                mma8(acc[1][nt], al[1], bh);
            }
        }
        if (st < 15) PHI_ST(buf ^ 1);
        __syncthreads();
    }

    // rowmax over 256 cols: reduce over tig (shfl), then across wn via smem
#pragma unroll
    for (int mt = 0; mt < 2; mt++) {
        float mlo = -1e30f, mhi = -1e30f;
#pragma unroll
        for (int nt = 0; nt < 16; nt++) {
            mlo = fmaxf(mlo, fmaxf(acc[mt][nt][0], acc[mt][nt][1]));
            mhi = fmaxf(mhi, fmaxf(acc[mt][nt][2], acc[mt][nt][3]));
        }
        mlo = fmaxf(mlo, __shfl_xor_sync(0xffffffffu, mlo, 1));
        mlo = fmaxf(mlo, __shfl_xor_sync(0xffffffffu, mlo, 2));
        mhi = fmaxf(mhi, __shfl_xor_sync(0xffffffffu, mhi, 1));
        mhi = fmaxf(mhi, __shfl_xor_sync(0xffffffffu, mhi, 2));
        const int rl = wm * 32 + mt * 16 + gid;
        if (tig == 0) { rmax[wn * 128 + rl] = mlo; rmax[wn * 128 + rl + 8] = mhi; }
    }
    __syncthreads();
#pragma unroll
    for (int mt = 0; mt < 2; mt++) {
        const int rl = wm * 32 + mt * 16 + gid, rh = rl + 8;
        const float Ml = fmaxf(rmax[rl], rmax[128 + rl]);
        const float Mh = fmaxf(rmax[rh], rmax[128 + rh]);
        float* pl = Phi + (row0 + rl) * MM;
        float* ph = Phi + (row0 + rh) * MM;
#pragma unroll
        for (int nt = 0; nt < 16; nt++) {
            const int col = wn * 128 + nt * 8 + tig * 2;
            float2 v0, v1;
            v0.x = tf32r(__expf(acc[mt][nt][0] - Ml) * 0.0625f);
            v0.y = tf32r(__expf(acc[mt][nt][1] - Ml) * 0.0625f);
            v1.x = tf32r(__expf(acc[mt][nt][2] - Mh) * 0.0625f);
            v1.y = tf32r(__expf(acc[mt][nt][3] - Mh) * 0.0625f);
            *(float2*)(pl + col) = v0;
            *(float2*)(ph + col) = v1;
        }
    }
}

// V -> tf32-rounded copy
__global__ void __launch_bounds__(256) vtrunc(const float* __restrict__ V)
{
    const size_t i = ((size_t)blockIdx.x * 256 + threadIdx.x) * 4;
    float4 v = *(const float4*)(V + i);
    v.x = tf32r(v.x); v.y = tf32r(v.y); v.z = tf32r(v.z); v.w = tf32r(v.w);
    *(float4*)(g_V32 + i) = v;
}

// z chunk sums
__global__ void __launch_bounds__(256) zsum_kernel()
{
    const int bc = blockIdx.x, m = threadIdx.x;
    const size_t base = (size_t)((bc >> 5) * SEQ + (bc & 31) * CHUNK) * MM;
    float s = 0.f;
#pragma unroll 8
    for (int k = 0; k < CHUNK; k++) s += g_phiK[base + (size_t)k * MM + m];
    g_z[(size_t)bc * MM + m] = s;
}

// ---------------------------------------------------------------------------
// Kernel 2: S_c[m][dv] = sum_k phiK[k][m] * V32[k][dv], K=128.
// grid (2 dv, 2 m, 256 bc). smem [k16][col] stride 136.
// ---------------------------------------------------------------------------
#define SC_SMEM ((2*2176 + 2*2176) * 4)

__global__ void __launch_bounds__(256) scontrib_mma()
{
    extern __shared__ float sm[];
    float* As = sm;            // 2 * 16*136 (phiK [k][m])
    float* Bs = As + 4352;     // 2 * 16*136 (V [k][dv])
    const uint32_t asb = su32(As), bsb = su32(Bs);

    const int tid = threadIdx.x;
    const int lane = tid & 31, w = tid >> 5;
    const int gid = lane >> 2, tig = lane & 3;
    const int wm = w >> 1, wn = w & 1;

    const int bc = blockIdx.z;
    const int m0c = blockIdx.y * 128, dv0 = blockIdx.x * 128;
    const size_t base = (size_t)(bc >> 5) * SEQ + (size_t)(bc & 31) * CHUNK;
    const float* pk = g_phiK + base * MM + m0c;
    const float* vv = g_V32 + base * DVV + dv0;

    float acc[2][8][4];
#pragma unroll
    for (int mt = 0; mt < 2; mt++)
#pragma unroll
        for (int nt = 0; nt < 8; nt++)
#pragma unroll
            for (int i = 0; i < 4; i++) acc[mt][nt][i] = 0.f;

#define SC_CP(st, bf) { \
    _Pragma("unroll") \
    for (int j = 0; j < 2; j++) { \
        const int idx = tid + j * 256; \
        const int r = idx >> 5, q = (idx & 31) * 4; \
        cpa(asb + ((bf) * 2176 + r * 136 + q) * 4, pk + ((st) * 16 + r) * MM + q); \
        cpa(bsb + ((bf) * 2176 + r * 136 + q) * 4, vv + ((st) * 16 + r) * DVV + q); \
    } \
    CP_COMMIT(); }

    SC_CP(0, 0);
#pragma unroll 1
    for (int st = 0; st < 8; st++) {
        const int buf = st & 1;
        if (st < 7) { SC_CP(st + 1, buf ^ 1); CP_WAIT1(); } else { CP_WAIT0(); }
        __syncthreads();
        const float* as = As + buf * 2176;
        const float* bs = Bs + buf * 2176;
#pragma unroll
        for (int k8 = 0; k8 < 16; k8 += 8) {
            uint32_t a[2][4];
#pragma unroll
            for (int mt = 0; mt < 2; mt++) {
                const int rb = wm * 32 + mt * 16;
                a[mt][0] = fb(as[(k8 + tig) * 136 + rb + gid]);
                a[mt][1] = fb(as[(k8 + tig) * 136 + rb + gid + 8]);
                a[mt][2] = fb(as[(k8 + tig + 4) * 136 + rb + gid]);
                a[mt][3] = fb(as[(k8 + tig + 4) * 136 + rb + gid + 8]);
            }
#pragma unroll
            for (int nt = 0; nt < 8; nt++) {
                const int nb = wn * 64 + nt * 8;
                uint32_t b[2] = { fb(bs[(k8 + tig) * 136 + nb + gid]),
                                  fb(bs[(k8 + tig + 4) * 136 + nb + gid]) };
                mma8(acc[0][nt], a[0], b);
                mma8(acc[1][nt], a[1], b);
            }
        }
        __syncthreads();
    }

    float* sout = g_S + (size_t)bc * (MM * DVV);
#pragma unroll
    for (int mt = 0; mt < 2; mt++) {
        const int m = m0c + wm * 32 + mt * 16 + gid;
#pragma unroll
        for (int nt = 0; nt < 8; nt++) {
            const int col = dv0 + wn * 64 + nt * 8 + tig * 2;
            *(float2*)(sout + (size_t)m * DVV + col) =
                make_float2(acc[mt][nt][0], acc[mt][nt][1]);
            *(float2*)(sout + (size_t)(m + 8) * DVV + col) =
                make_float2(acc[mt][nt][2], acc[mt][nt][3]);
        }
    }
}

// exclusive prefixes over chunks; S prefixes stored tf32-rounded
__global__ void __launch_bounds__(256) prefixS_kernel()
{
    const size_t g = (size_t)blockIdx.x * 256 + threadIdx.x;
    const size_t b = g >> 16, r = g & 65535;
    float* p = g_S + b * (size_t)NCHUNK * 65536 + r;
    float v[NCHUNK];
#pragma unroll
    for (int c = 0; c < NCHUNK; c++) v[c] = p[(size_t)c * 65536];
    float run = 0.f;
#pragma unroll
    for (int c = 0; c < NCHUNK; c++) { float t = v[c]; v[c] = tf32r(run); run += t; }
#pragma unroll
    for (int c = 0; c < NCHUNK; c++) p[(size_t)c * 65536] = v[c];
}
__global__ void __launch_bounds__(256) prefixz_kernel()
{
    const int g = blockIdx.x * 256 + threadIdx.x;
    const int b = g / MM, m = g % MM;
    float* p = g_z + (size_t)b * NCHUNK * MM + m;
    float v[NCHUNK];
#pragma unroll
    for (int c = 0; c < NCHUNK; c++) v[c] = p[c * MM];
    float run = 0.f;
#pragma unroll
    for (int c = 0; c < NCHUNK; c++) { float t = v[c]; v[c] = run; run += t; }
#pragma unroll
    for (int c = 0; c < NCHUNK; c++) p[c * MM] = v[c];
}

// ---------------------------------------------------------------------------
// Kernel 3: inter raw  Out[t][dv] = sum_m phiQ[t][m]*Spre[m][dv], K=256.
// Also (blockIdx.x==0): g_den[bc][t] = sum_m phiQ[t][m]*zpre[m].
// grid (2 dv, 256 bc). A [row][k16] stride 20; B [k16][dv] stride 136.
// ---------------------------------------------------------------------------
#define IN_SMEM ((2*2560 + 2*2176 + 256 + 256) * 4)

__global__ void __launch_bounds__(256) inter_mma(float* __restrict__ Out)
{
    extern __shared__ float sm[];
    float* Aq = sm;             // 2 * 128*20
    float* Bs = Aq + 5120;      // 2 * 16*136
    float* zsm = Bs + 4352;     // 256
    float* dpart = zsm + 256;   // 256
    const uint32_t aqb = su32(Aq), bsb = su32(Bs);

    const int tid = threadIdx.x;
    const int lane = tid & 31, w = tid >> 5;
    const int gid = lane >> 2, tig = lane & 3;
    const int wm = w >> 1, wn = w & 1;

    const int bc = blockIdx.y, dv0 = blockIdx.x * 128;
    const bool do_den = (blockIdx.x == 0);
    const size_t base = (size_t)(bc >> 5) * SEQ + (size_t)(bc & 31) * CHUNK;
    const float* pq = g_phiQ + base * MM;
    const float* sS = g_S + (size_t)bc * (MM * DVV) + dv0;

    zsm[tid] = g_z[(size_t)bc * MM + tid];

    float acc[2][8][4];
#pragma unroll
    for (int mt = 0; mt < 2; mt++)
#pragma unroll
        for (int nt = 0; nt < 8; nt++)
#pragma unroll
            for (int i = 0; i < 4; i++) acc[mt][nt][i] = 0.f;
    float dp = 0.f;
    const int dr = tid >> 1, dh = tid & 1;

#define IN_CP(st, bf) { \
    _Pragma("unroll") \
    for (int j = 0; j < 2; j++) { \
        const int idx = tid + j * 256; \
        { const int r = idx >> 2, q = (idx & 3) * 4; \
          cpa(aqb + ((bf) * 2560 + r * 20 + q) * 4, pq + r * MM + (st) * 16 + q); } \
        { const int r = idx >> 5, q = (idx & 31) * 4; \
          cpa(bsb + ((bf) * 2176 + r * 136 + q) * 4, sS + ((st) * 16 + r) * DVV + q); } \
    } \
    CP_COMMIT(); }

    IN_CP(0, 0);
#pragma unroll 1
    for (int st = 0; st < 16; st++) {
        const int buf = st & 1;
        if (st < 15) { IN_CP(st + 1, buf ^ 1); CP_WAIT1(); } else { CP_WAIT0(); }
        __syncthreads();
        const float* aq = Aq + buf * 2560;
        const float* bs = Bs + buf * 2176;
#pragma unroll
        for (int k8 = 0; k8 < 16; k8 += 8) {
            uint32_t a[2][4];
#pragma unroll
            for (int mt = 0; mt < 2; mt++) {
                const int rb = wm * 32 + mt * 16;
                a[mt][0] = fb(aq[(rb + gid) * 20 + k8 + tig]);
                a[mt][1] = fb(aq[(rb + gid + 8) * 20 + k8 + tig]);
                a[mt][2] = fb(aq[(rb + gid) * 20 + k8 + tig + 4]);
                a[mt][3] = fb(aq[(rb + gid + 8) * 20 + k8 + tig + 4]);
            }
#pragma unroll
            for (int nt = 0; nt < 8; nt++) {
                const int nb = wn * 64 + nt * 8;
                uint32_t b[2] = { fb(bs[(k8 + tig) * 136 + nb + gid]),
                                  fb(bs[(k8 + tig + 4) * 136 + nb + gid]) };
                mma8(acc[0][nt], a[0], b);
                mma8(acc[1][nt], a[1], b);
            }
        }
        if (do_den) {
#pragma unroll
            for (int j = 0; j < 8; j++)
                dp = fmaf(aq[dr * 20 + dh * 8 + j], zsm[st * 16 + dh * 8 + j], dp);
        }
        __syncthreads();
    }

    if (do_den) {
        dpart[tid] = dp;
        __syncthreads();
        if (tid < 128)
            g_den[(size_t)bc * CHUNK + tid] = dpart[2 * tid] + dpart[2 * tid + 1];
    }

#pragma unroll
    for (int mt = 0; mt < 2; mt++) {
        const int t = wm * 32 + mt * 16 + gid;
#pragma unroll
        for (int nt = 0; nt < 8; nt++) {
            const int col = dv0 + wn * 64 + nt * 8 + tig * 2;
            *(float2*)(Out + (base + t) * DVV + col) =
                make_float2(acc[mt][nt][0], acc[mt][nt][1]);
            *(float2*)(Out + (base + t + 8) * DVV + col) =
                make_float2(acc[mt][nt][2], acc[mt][nt][3]);
        }
    }
}

// ---------------------------------------------------------------------------
// Kernel 4: per (b,chunk):
//   Phase A: A = tril(Pq Pk^T), K=256; tf32-round, rowsum -> den; A -> smem.
//   Phase B: intra = A @ V; Out = (intra + Out_raw) / den.
// grid 256. smem: Aq/Bk (phase A tiles, reused as V tiles), As2 [t][s] str 132.
// ---------------------------------------------------------------------------
#define CH_SMEM ((5120 + 5120 + 16896 + 256 + 128) * 4)

__global__ void __launch_bounds__(256) chunk_mma(float* __restrict__ Out)
{
    extern __shared__ float sm[];
    float* Aq  = sm;              // 2*128*20 = 5120 (phase B: V tiles 2*16*264=8448 from here)
    float* Bk  = Aq + 5120;       // 2*128*20 = 5120
    float* As2 = Bk + 5120;       // 128*132 = 16896
    float* rsh = As2 + 16896;     // 256
    float* rden = rsh + 256;      // 128
    const uint32_t aqb = su32(Aq), bkb = su32(Bk), vsb = su32(Aq);

    const int tid = threadIdx.x;
    const int lane = tid & 31, w = tid >> 5;
    const int gid = lane >> 2, tig = lane & 3;
    const int wm = w >> 1, wn = w & 1;

    const int bc = blockIdx.x;
    const size_t base = (size_t)(bc >> 5) * SEQ + (size_t)(bc & 31) * CHUNK;
    const float* pq = g_phiQ + base * MM;
    const float* pk = g_phiK + base * MM;
    const float* Vb = g_V32 + base * DVV;

    float acc[2][8][4];
#pragma unroll
    for (int mt = 0; mt < 2; mt++)
#pragma unroll
        for (int nt = 0; nt < 8; nt++)
#pragma unroll
            for (int i = 0; i < 4; i++) acc[mt][nt][i] = 0.f;

#define CA_CP(st, bf) { \
    _Pragma("unroll") \
    for (int j = 0; j < 2; j++) { \
        const int idx = tid + j * 256; \
        const int r = idx >> 2, q = (idx & 3) * 4; \
        cpa(aqb + ((bf) * 2560 + r * 20 + q) * 4, pq + r * MM + (st) * 16 + q); \
        cpa(bkb + ((bf) * 2560 + r * 20 + q) * 4, pk + r * MM + (st) * 16 + q); \
    } \
    CP_COMMIT(); }

    CA_CP(0, 0);
#pragma unroll 1
    for (int st = 0; st < 16; st++) {
        const int buf = st & 1;
        if (st < 15) { CA_CP(st + 1, buf ^ 1); CP_WAIT1(); } else { CP_WAIT0(); }
        __syncthreads();
        const float* aq = Aq + buf * 2560;
        const float* bk = Bk + buf * 2560;
#pragma unroll
        for (int k8 = 0; k8 < 16; k8 += 8) {
            uint32_t a[2][4];
#pragma unroll
            for (int mt = 0; mt < 2; mt++) {
                const int rb = wm * 32 + mt * 16;
                a[mt][0] = fb(aq[(rb + gid) * 20 + k8 + tig]);
                a[mt][1] = fb(aq[(rb + gid + 8) * 20 + k8 + tig]);
                a[mt][2] = fb(aq[(rb + gid) * 20 + k8 + tig + 4]);
                a[mt][3] = fb(aq[(rb + gid + 8) * 20 + k8 + tig + 4]);
            }
#pragma unroll
            for (int nt = 0; nt < 8; nt++) {
                const int nb = wn * 64 + nt * 8;
                uint32_t b[2] = { fb(bk[(nb + gid) * 20 + k8 + tig]),
                                  fb(bk[(nb + gid) * 20 + k8 + tig + 4]) };
                mma8(acc[0][nt], a[0], b);
                mma8(acc[1][nt], a[1], b);
            }
        }
        __syncthreads();
    }

    // start V prefetch for phase B (overlaps epilogue); Aq region reused
#define CB_CP(st, bf) { \
    _Pragma("unroll") \
    for (int j = 0; j < 4; j++) { \
        const int idx = tid + j * 256; \
        const int r = idx >> 6, qc = (idx & 63) * 4; \
        cpa(vsb + ((bf) * 4224 + r * 264 + qc) * 4, Vb + ((st) * 16 + r) * DVV + qc); \
    } \
    CP_COMMIT(); }

    CB_CP(0, 0);

    // phase A epilogue: mask, tf32-round, rowsum, stash into As2
#pragma unroll
    for (int mt = 0; mt < 2; mt++) {
        const int row = wm * 32 + mt * 16 + gid, row2 = row + 8;
        float rs1 = 0.f, rs2 = 0.f;
#pragma unroll
        for (int nt = 0; nt < 8; nt++) {
            const int col = wn * 64 + nt * 8 + tig * 2;
            float v0 = (col     <= row)  ? tf32r(acc[mt][nt][0]) : 0.f;
            float v1 = (col + 1 <= row)  ? tf32r(acc[mt][nt][1]) : 0.f;
            float v2 = (col     <= row2) ? tf32r(acc[mt][nt][2]) : 0.f;
            float v3 = (col + 1 <= row2) ? tf32r(acc[mt][nt][3]) : 0.f;
            rs1 += v0 + v1; rs2 += v2 + v3;
            *(float2*)(As2 + row * 132 + col) = make_float2(v0, v1);
            *(float2*)(As2 + row2 * 132 + col) = make_float2(v2, v3);
        }
        rs1 += __shfl_xor_sync(0xffffffffu, rs1, 1);
        rs1 += __shfl_xor_sync(0xffffffffu, rs1, 2);
        rs2 += __shfl_xor_sync(0xffffffffu, rs2, 1);
        rs2 += __shfl_xor_sync(0xffffffffu, rs2, 2);
        if (tig == 0) { rsh[wn * 128 + row] = rs1; rsh[wn * 128 + row2] = rs2; }
    }
    __syncthreads();
    if (tid < 128)
        rden[tid] = 1.f / fmaxf(g_den[(size_t)bc * CHUNK + tid] + rsh[tid] + rsh[128 + tid], 1e-6f);

    // phase B: intra = As2 @ V, 8 stages of 16 s
    float acc2[2][16][4];
#pragma unroll
    for (int mt = 0; mt < 2; mt++)
#pragma unroll
        for (int nt = 0; nt < 16; nt++)
#pragma unroll
            for (int i = 0; i < 4; i++) acc2[mt][nt][i] = 0.f;

#pragma unroll 1
    for (int st = 0; st < 8; st++) {
        const int buf = st & 1;
        if (st < 7) { CB_CP(st + 1, buf ^ 1); CP_WAIT1(); } else { CP_WAIT0(); }
        __syncthreads();
        const float* vs = Aq + buf * 4224;
#pragma unroll
        for (int k8 = 0; k8 < 16; k8 += 8) {
            const int kg = st * 16 + k8;
            uint32_t a[2][4];
#pragma unroll
            for (int mt = 0; mt < 2; mt++) {
                const int rb = wm * 32 + mt * 16;
                a[mt][0] = fb(As2[(rb + gid) * 132 + kg + tig]);
                a[mt][1] = fb(As2[(rb + gid + 8) * 132 + kg + tig]);
                a[mt][2] = fb(As2[(rb + gid) * 132 + kg + tig + 4]);
                a[mt][3] = fb(As2[(rb + gid + 8) * 132 + kg + tig + 4]);
            }
#pragma unroll
            for (int nt = 0; nt < 16; nt++) {
                const int nb = wn * 128 + nt * 8;
                uint32_t b[2] = { fb(vs[(k8 + tig) * 264 + nb + gid]),
                                  fb(vs[(k8 + tig + 4) * 264 + nb + gid]) };
                mma8(acc2[0][nt], a[0], b);
                mma8(acc2[1][nt], a[1], b);
            }
        }
        __syncthreads();
    }

    // final: Out = (intra + inter_raw) * rden
#pragma unroll
    for (int mt = 0; mt < 2; mt++) {
        const int t = wm * 32 + mt * 16 + gid, t2 = t + 8;
        const float r1 = rden[t], r2 = rden[t2];
#pragma unroll
        for (int nt = 0; nt < 16; nt++) {
            const int col = wn * 128 + nt * 8 + tig * 2;
            float2* p1 = (float2*)(Out + (base + t) * DVV + col);
            float2* p2 = (float2*)(Out + (base + t2) * DVV + col);
            float2 i1 = *p1, i2 = *p2;
            *p1 = make_float2((acc2[mt][nt][0] + i1.x) * r1, (acc2[mt][nt][1] + i1.y) * r1);
            *p2 = make_float2((acc2[mt][nt][2] + i2.x) * r2, (acc2[mt][nt][3] + i2.y) * r2);
        }
    }
}

// ---------------------------------------------------------------------------
extern "C" void kernel_launch(void* const* d_in, const int* in_sizes, int n_in,
                              void* d_out, int out_size)
{
    (void)in_sizes; (void)n_in; (void)out_size;
    const float* Q   = (const float*)d_in[0];
    const float* Kin = (const float*)d_in[1];
    const float* V   = (const float*)d_in[2];
    const float* W   = (const float*)d_in[3];
    float* Out = (float*)d_out;

    cudaFuncSetAttribute(phi_mma,   cudaFuncAttributeMaxDynamicSharedMemorySize, PHI_SMEM);
    cudaFuncSetAttribute(chunk_mma, cudaFuncAttributeMaxDynamicSharedMemorySize, CH_SMEM);

    phi_mma<<<512, 256, PHI_SMEM>>>(Q, Kin, W);
    vtrunc<<<BATCH * SEQ * DVV / 1024, 256>>>(V);
    zsum_kernel<<<BATCH * NCHUNK, 256>>>();
    scontrib_mma<<<dim3(2, 2, BATCH * NCHUNK), 256, SC_SMEM>>>();
    prefixS_kernel<<<(BATCH * MM * DVV) / 256, 256>>>();
    prefixz_kernel<<<(BATCH * MM) / 256, 256>>>();
    inter_mma<<<dim3(2, BATCH * NCHUNK), 256, IN_SMEM>>>(Out);
    chunk_mma<<<BATCH * NCHUNK, 256, CH_SMEM>>>(Out);
}

// round 7
// speedup vs baseline: 2.6639x; 1.0865x over previous
#include <cuda_runtime.h>
#include <cuda_bf16.h>
#include <cstdint>

// Performer (FAVOR+) causal attention — mma.sync (HMMA) implementation.
// (tcgen05 unavailable: harness builds compute_103 PTX, no 'a' features.)
// B=8, N=4096, D=256, M=256, DV=256. Chunk C=128, NC=32.
//
// out = (tril(Pq Pk^T) V + Pq S_pre) / (rowsum(tril(Pq Pk^T)) + Pq z_pre)
// phi(x) = exp(proj - rowmax(proj))/16      (|x|^2 cancels in the shift)
//
// phi projection: 3xBF16 split (hh+hl+lh) on m16n8k16 — 2x the flops/instr
// of tf32 at ~1e-4 proj error. All downstream MMAs are tf32 with operands
// pre-rounded to exact tf32 so num/den weight sets match and rounding cancels.

#define BATCH 8
#define SEQ   4096
#define DD    256
#define MM    256
#define DVV   256
#define CHUNK 128
#define NCHUNK 32

__device__ float g_phiQ[BATCH * SEQ * MM];
__device__ float g_phiK[BATCH * SEQ * MM];
__device__ float g_V32 [BATCH * SEQ * DVV];
__device__ float g_S   [BATCH * NCHUNK * MM * DVV];   // [bc][m][dv]
__device__ float g_z   [BATCH * NCHUNK * MM];
__device__ float g_den [BATCH * NCHUNK * CHUNK];      // den_inter per row

__device__ __forceinline__ uint32_t su32(const void* p) {
    uint32_t a;
    asm("{ .reg .u64 t; cvta.to.shared.u64 t, %1; cvt.u32.u64 %0, t; }" : "=r"(a) : "l"(p));
    return a;
}
__device__ __forceinline__ void cpa(uint32_t d, const float* s) {
    asm volatile("cp.async.cg.shared.global [%0], [%1], 16;" :: "r"(d), "l"(s));
}
#define CP_COMMIT() asm volatile("cp.async.commit_group;" ::: "memory")
#define CP_WAIT1()  asm volatile("cp.async.wait_group 1;" ::: "memory")
#define CP_WAIT0()  asm volatile("cp.async.wait_group 0;" ::: "memory")

__device__ __forceinline__ float tf32r(float x) {
    uint32_t h; asm("cvt.rna.tf32.f32 %0, %1;" : "=r"(h) : "f"(x));
    return __uint_as_float(h);
}
__device__ __forceinline__ void mma8(float* c, const uint32_t* a, const uint32_t* b) {
    asm volatile(
        "mma.sync.aligned.m16n8k8.row.col.f32.tf32.tf32.f32 "
        "{%0,%1,%2,%3},{%4,%5,%6,%7},{%8,%9},{%0,%1,%2,%3};"
        : "+f"(c[0]), "+f"(c[1]), "+f"(c[2]), "+f"(c[3])
        : "r"(a[0]), "r"(a[1]), "r"(a[2]), "r"(a[3]), "r"(b[0]), "r"(b[1]));
}
__device__ __forceinline__ void mma16(float* c, const uint32_t* a, const uint32_t* b) {
    asm volatile(
        "mma.sync.aligned.m16n8k16.row.col.f32.bf16.bf16.f32 "
        "{%0,%1,%2,%3},{%4,%5,%6,%7},{%8,%9},{%0,%1,%2,%3};"
        : "+f"(c[0]), "+f"(c[1]), "+f"(c[2]), "+f"(c[3])
        : "r"(a[0]), "r"(a[1]), "r"(a[2]), "r"(a[3]), "r"(b[0]), "r"(b[1]));
}
__device__ __forceinline__ uint32_t fb(float x) { return __float_as_uint(x); }

// split x0,x1 into bf16 hi + bf16 lo residual, packed (x0 -> low half)
__device__ __forceinline__ void split_pack(float x0, float x1, uint32_t& hp, uint32_t& lp) {
    __nv_bfloat16 h0 = __float2bfloat16_rn(x0);
    __nv_bfloat16 h1 = __float2bfloat16_rn(x1);
    float f0 = __bfloat162float(h0), f1 = __bfloat162float(h1);
    __nv_bfloat16 l0 = __float2bfloat16_rn(x0 - f0);
    __nv_bfloat16 l1 = __float2bfloat16_rn(x1 - f1);
    hp = ((uint32_t)__bfloat16_as_ushort(h1) << 16) | __bfloat16_as_ushort(h0);
    lp = ((uint32_t)__bfloat16_as_ushort(l1) << 16) | __bfloat16_as_ushort(l0);
}

// ---------------------------------------------------------------------------
// Kernel 1: phi = exp(X @ W^T - rowmax)/16, 3xBF16 (m16n8k16).
// grid 512 (bid<256 -> Q else K_in). CTA 128 rows x 256 cols, K=256.
// Warps 4x2 (wm,wn); warp tile 32x128. smem: u32 bf16-pairs, [row][ku] str 12.
// 16 stages of K=16 (8 u32/row), double buffered.
// ---------------------------------------------------------------------------
#define PHI_SMEM ((3072*2 + 6144*2 + 256) * 4)

__global__ void __launch_bounds__(256) phi_mma(const float* __restrict__ Q,
                                               const float* __restrict__ Kin,
                                               const float* __restrict__ W)
{
    extern __shared__ uint32_t smu[];
    uint32_t* Xh = smu;             // 2 bufs * 128*12
    uint32_t* Xl = Xh + 3072;
    uint32_t* Wh = Xl + 3072;       // 2 bufs * 256*12
    uint32_t* Wl = Wh + 6144;
    float* rmax = (float*)(Wl + 6144);   // 256

    const int tid = threadIdx.x;
    const int lane = tid & 31, w = tid >> 5;
    const int gid = lane >> 2, tig = lane & 3;
    const int wm = w >> 1, wn = w & 1;

    const int bid = blockIdx.x;
    const float* X = (bid < 256) ? Q : Kin;
    float* Phi = (bid < 256) ? g_phiQ : g_phiK;
    const size_t row0 = (size_t)(bid & 255) * 128;

    float acc[2][16][4];
#pragma unroll
    for (int mt = 0; mt < 2; mt++)
#pragma unroll
        for (int nt = 0; nt < 16; nt++)
#pragma unroll
            for (int i = 0; i < 4; i++) acc[mt][nt][i] = 0.f;

    const int xr = tid >> 1, xc = (tid & 1) * 8;
    const float* xsrc = X + (row0 + xr) * DD + xc;
    const float* wsrc = W + (size_t)tid * DD;

    float4 rx0, rx1, rw0, rw1, rw2, rw3;

#define PHI_LD(st) { \
    const float* p = xsrc + (st) * 16; \
    rx0 = *(const float4*)p; rx1 = *(const float4*)(p + 4); \
    const float* q = wsrc + (st) * 16; \
    rw0 = *(const float4*)q;       rw1 = *(const float4*)(q + 4); \
    rw2 = *(const float4*)(q + 8); rw3 = *(const float4*)(q + 12); }

#define PHI_ST(bf) { \
    uint32_t* dxh = Xh + (bf) * 1536 + xr * 12 + (xc >> 1); \
    uint32_t* dxl = Xl + (bf) * 1536 + xr * 12 + (xc >> 1); \
    split_pack(rx0.x, rx0.y, dxh[0], dxl[0]); \
    split_pack(rx0.z, rx0.w, dxh[1], dxl[1]); \
    split_pack(rx1.x, rx1.y, dxh[2], dxl[2]); \
    split_pack(rx1.z, rx1.w, dxh[3], dxl[3]); \
    uint32_t* dwh = Wh + (bf) * 3072 + tid * 12; \
    uint32_t* dwl = Wl + (bf) * 3072 + tid * 12; \
    split_pack(rw0.x, rw0.y, dwh[0], dwl[0]); \
    split_pack(rw0.z, rw0.w, dwh[1], dwl[1]); \
    split_pack(rw1.x, rw1.y, dwh[2], dwl[2]); \
    split_pack(rw1.z, rw1.w, dwh[3], dwl[3]); \
    split_pack(rw2.x, rw2.y, dwh[4], dwl[4]); \
    split_pack(rw2.z, rw2.w, dwh[5], dwl[5]); \
    split_pack(rw3.x, rw3.y, dwh[6], dwl[6]); \
    split_pack(rw3.z, rw3.w, dwh[7], dwl[7]); }

    PHI_LD(0); PHI_ST(0);
    __syncthreads();

#pragma unroll 1
    for (int st = 0; st < 16; st++) {
        const int buf = st & 1;
        if (st < 15) PHI_LD(st + 1);

        const uint32_t* xh = Xh + buf * 1536;
        const uint32_t* xl = Xl + buf * 1536;
        const uint32_t* wh = Wh + buf * 3072;
        const uint32_t* wl = Wl + buf * 3072;

        uint32_t ah[2][4], al[2][4];
#pragma unroll
        for (int mt = 0; mt < 2; mt++) {
            const int rb = wm * 32 + mt * 16;
            ah[mt][0] = xh[(rb + gid) * 12 + tig];
            ah[mt][1] = xh[(rb + gid + 8) * 12 + tig];
            ah[mt][2] = xh[(rb + gid) * 12 + tig + 4];
            ah[mt][3] = xh[(rb + gid + 8) * 12 + tig + 4];
            al[mt][0] = xl[(rb + gid) * 12 + tig];
            al[mt][1] = xl[(rb + gid + 8) * 12 + tig];
            al[mt][2] = xl[(rb + gid) * 12 + tig + 4];
            al[mt][3] = xl[(rb + gid + 8) * 12 + tig + 4];
        }
#pragma unroll
        for (int nt = 0; nt < 16; nt++) {
            const int nb = wn * 128 + nt * 8;
            uint32_t bh[2] = { wh[(nb + gid) * 12 + tig], wh[(nb + gid) * 12 + tig + 4] };
            uint32_t bl[2] = { wl[(nb + gid) * 12 + tig], wl[(nb + gid) * 12 + tig + 4] };
            mma16(acc[0][nt], ah[0], bh);
            mma16(acc[1][nt], ah[1], bh);
            mma16(acc[0][nt], ah[0], bl);
            mma16(acc[1][nt], ah[1], bl);
            mma16(acc[0][nt], al[0], bh);
            mma16(acc[1][nt], al[1], bh);
        }
        if (st < 15) PHI_ST(buf ^ 1);
        __syncthreads();
    }

    // rowmax over 256 cols: reduce over tig (shfl), then across wn via smem
#pragma unroll
    for (int mt = 0; mt < 2; mt++) {
        float mlo = -1e30f, mhi = -1e30f;
#pragma unroll
        for (int nt = 0; nt < 16; nt++) {
            mlo = fmaxf(mlo, fmaxf(acc[mt][nt][0], acc[mt][nt][1]));
            mhi = fmaxf(mhi, fmaxf(acc[mt][nt][2], acc[mt][nt][3]));
        }
        mlo = fmaxf(mlo, __shfl_xor_sync(0xffffffffu, mlo, 1));
        mlo = fmaxf(mlo, __shfl_xor_sync(0xffffffffu, mlo, 2));
        mhi = fmaxf(mhi, __shfl_xor_sync(0xffffffffu, mhi, 1));
        mhi = fmaxf(mhi, __shfl_xor_sync(0xffffffffu, mhi, 2));
        const int rl = wm * 32 + mt * 16 + gid;
        if (tig == 0) { rmax[wn * 128 + rl] = mlo; rmax[wn * 128 + rl + 8] = mhi; }
    }
    __syncthreads();
#pragma unroll
    for (int mt = 0; mt < 2; mt++) {
        const int rl = wm * 32 + mt * 16 + gid, rh = rl + 8;
        const float Ml = fmaxf(rmax[rl], rmax[128 + rl]);
        const float Mh = fmaxf(rmax[rh], rmax[128 + rh]);
        float* pl = Phi + (row0 + rl) * MM;
        float* ph = Phi + (row0 + rh) * MM;
#pragma unroll
        for (int nt = 0; nt < 16; nt++) {
            const int col = wn * 128 + nt * 8 + tig * 2;
            float2 v0, v1;
            v0.x = tf32r(__expf(acc[mt][nt][0] - Ml) * 0.0625f);
            v0.y = tf32r(__expf(acc[mt][nt][1] - Ml) * 0.0625f);
            v1.x = tf32r(__expf(acc[mt][nt][2] - Mh) * 0.0625f);
            v1.y = tf32r(__expf(acc[mt][nt][3] - Mh) * 0.0625f);
            *(float2*)(pl + col) = v0;
            *(float2*)(ph + col) = v1;
        }
    }
}

// V -> tf32-rounded copy
__global__ void __launch_bounds__(256) vtrunc(const float* __restrict__ V)
{
    const size_t i = ((size_t)blockIdx.x * 256 + threadIdx.x) * 4;
    float4 v = *(const float4*)(V + i);
    v.x = tf32r(v.x); v.y = tf32r(v.y); v.z = tf32r(v.z); v.w = tf32r(v.w);
    *(float4*)(g_V32 + i) = v;
}

// z chunk sums
__global__ void __launch_bounds__(256) zsum_kernel()
{
    const int bc = blockIdx.x, m = threadIdx.x;
    const size_t base = (size_t)((bc >> 5) * SEQ + (bc & 31) * CHUNK) * MM;
    float s = 0.f;
#pragma unroll 8
    for (int k = 0; k < CHUNK; k++) s += g_phiK[base + (size_t)k * MM + m];
    g_z[(size_t)bc * MM + m] = s;
}

// ---------------------------------------------------------------------------
// Kernel 2: S_c[m][dv] = sum_k phiK[k][m] * V32[k][dv], K=128.
// grid (2 dv, 2 m, 256 bc). smem [k16][col] stride 136.
// ---------------------------------------------------------------------------
#define SC_SMEM ((2*2176 + 2*2176) * 4)

__global__ void __launch_bounds__(256) scontrib_mma()
{
    extern __shared__ float sm[];
    float* As = sm;            // 2 * 16*136 (phiK [k][m])
    float* Bs = As + 4352;     // 2 * 16*136 (V [k][dv])
    const uint32_t asb = su32(As), bsb = su32(Bs);

    const int tid = threadIdx.x;
    const int lane = tid & 31, w = tid >> 5;
    const int gid = lane >> 2, tig = lane & 3;
    const int wm = w >> 1, wn = w & 1;

    const int bc = blockIdx.z;
    const int m0c = blockIdx.y * 128, dv0 = blockIdx.x * 128;
    const size_t base = (size_t)(bc >> 5) * SEQ + (size_t)(bc & 31) * CHUNK;
    const float* pk = g_phiK + base * MM + m0c;
    const float* vv = g_V32 + base * DVV + dv0;

    float acc[2][8][4];
#pragma unroll
    for (int mt = 0; mt < 2; mt++)
#pragma unroll
        for (int nt = 0; nt < 8; nt++)
#pragma unroll
            for (int i = 0; i < 4; i++) acc[mt][nt][i] = 0.f;

#define SC_CP(st, bf) { \
    _Pragma("unroll") \
    for (int j = 0; j < 2; j++) { \
        const int idx = tid + j * 256; \
        const int r = idx >> 5, q = (idx & 31) * 4; \
        cpa(asb + ((bf) * 2176 + r * 136 + q) * 4, pk + ((st) * 16 + r) * MM + q); \
        cpa(bsb + ((bf) * 2176 + r * 136 + q) * 4, vv + ((st) * 16 + r) * DVV + q); \
    } \
    CP_COMMIT(); }

    SC_CP(0, 0);
#pragma unroll 1
    for (int st = 0; st < 8; st++) {
        const int buf = st & 1;
        if (st < 7) { SC_CP(st + 1, buf ^ 1); CP_WAIT1(); } else { CP_WAIT0(); }
        __syncthreads();
        const float* as = As + buf * 2176;
        const float* bs = Bs + buf * 2176;
#pragma unroll
        for (int k8 = 0; k8 < 16; k8 += 8) {
            uint32_t a[2][4];
#pragma unroll
            for (int mt = 0; mt < 2; mt++) {
                const int rb = wm * 32 + mt * 16;
                a[mt][0] = fb(as[(k8 + tig) * 136 + rb + gid]);
                a[mt][1] = fb(as[(k8 + tig) * 136 + rb + gid + 8]);
                a[mt][2] = fb(as[(k8 + tig + 4) * 136 + rb + gid]);
                a[mt][3] = fb(as[(k8 + tig + 4) * 136 + rb + gid + 8]);
            }
#pragma unroll
            for (int nt = 0; nt < 8; nt++) {
                const int nb = wn * 64 + nt * 8;
                uint32_t b[2] = { fb(bs[(k8 + tig) * 136 + nb + gid]),
                                  fb(bs[(k8 + tig + 4) * 136 + nb + gid]) };
                mma8(acc[0][nt], a[0], b);
                mma8(acc[1][nt], a[1], b);
            }
        }
        __syncthreads();
    }

    float* sout = g_S + (size_t)bc * (MM * DVV);
#pragma unroll
    for (int mt = 0; mt < 2; mt++) {
        const int m = m0c + wm * 32 + mt * 16 + gid;
#pragma unroll
        for (int nt = 0; nt < 8; nt++) {
            const int col = dv0 + wn * 64 + nt * 8 + tig * 2;
            *(float2*)(sout + (size_t)m * DVV + col) =
                make_float2(acc[mt][nt][0], acc[mt][nt][1]);
            *(float2*)(sout + (size_t)(m + 8) * DVV + col) =
                make_float2(acc[mt][nt][2], acc[mt][nt][3]);
        }
    }
}

// exclusive prefixes over chunks; S prefixes stored tf32-rounded
__global__ void __launch_bounds__(256) prefixS_kernel()
{
    const size_t g = (size_t)blockIdx.x * 256 + threadIdx.x;
    const size_t b = g >> 16, r = g & 65535;
    float* p = g_S + b * (size_t)NCHUNK * 65536 + r;
    float v[NCHUNK];
#pragma unroll
    for (int c = 0; c < NCHUNK; c++) v[c] = p[(size_t)c * 65536];
    float run = 0.f;
#pragma unroll
    for (int c = 0; c < NCHUNK; c++) { float t = v[c]; v[c] = tf32r(run); run += t; }
#pragma unroll
    for (int c = 0; c < NCHUNK; c++) p[(size_t)c * 65536] = v[c];
}
__global__ void __launch_bounds__(256) prefixz_kernel()
{
    const int g = blockIdx.x * 256 + threadIdx.x;
    const int b = g / MM, m = g % MM;
    float* p = g_z + (size_t)b * NCHUNK * MM + m;
    float v[NCHUNK];
#pragma unroll
    for (int c = 0; c < NCHUNK; c++) v[c] = p[c * MM];
    float run = 0.f;
#pragma unroll
    for (int c = 0; c < NCHUNK; c++) { float t = v[c]; v[c] = run; run += t; }
#pragma unroll
    for (int c = 0; c < NCHUNK; c++) p[c * MM] = v[c];
}

// ---------------------------------------------------------------------------
// Kernel 3: inter raw  Out[t][dv] = sum_m phiQ[t][m]*Spre[m][dv], K=256.
// Also (blockIdx.x==0): g_den[bc][t] = sum_m phiQ[t][m]*zpre[m].
// grid (2 dv, 256 bc). A [row][k16] stride 20; B [k16][dv] stride 136.
// ---------------------------------------------------------------------------
#define IN_SMEM ((2*2560 + 2*2176 + 256 + 256) * 4)

__global__ void __launch_bounds__(256) inter_mma(float* __restrict__ Out)
{
    extern __shared__ float sm[];
    float* Aq = sm;             // 2 * 128*20
    float* Bs = Aq + 5120;      // 2 * 16*136
    float* zsm = Bs + 4352;     // 256
    float* dpart = zsm + 256;   // 256
    const uint32_t aqb = su32(Aq), bsb = su32(Bs);

    const int tid = threadIdx.x;
    const int lane = tid & 31, w = tid >> 5;
    const int gid = lane >> 2, tig = lane & 3;
    const int wm = w >> 1, wn = w & 1;

    const int bc = blockIdx.y, dv0 = blockIdx.x * 128;
    const bool do_den = (blockIdx.x == 0);
    const size_t base = (size_t)(bc >> 5) * SEQ + (size_t)(bc & 31) * CHUNK;
    const float* pq = g_phiQ + base * MM;
    const float* sS = g_S + (size_t)bc * (MM * DVV) + dv0;

    zsm[tid] = g_z[(size_t)bc * MM + tid];

    float acc[2][8][4];
#pragma unroll
    for (int mt = 0; mt < 2; mt++)
#pragma unroll
        for (int nt = 0; nt < 8; nt++)
#pragma unroll
            for (int i = 0; i < 4; i++) acc[mt][nt][i] = 0.f;
    float dp = 0.f;
    const int dr = tid >> 1, dh = tid & 1;

#define IN_CP(st, bf) { \
    _Pragma("unroll") \
    for (int j = 0; j < 2; j++) { \
        const int idx = tid + j * 256; \
        { const int r = idx >> 2, q = (idx & 3) * 4; \
          cpa(aqb + ((bf) * 2560 + r * 20 + q) * 4, pq + r * MM + (st) * 16 + q); } \
        { const int r = idx >> 5, q = (idx & 31) * 4; \
          cpa(bsb + ((bf) * 2176 + r * 136 + q) * 4, sS + ((st) * 16 + r) * DVV + q); } \
    } \
    CP_COMMIT(); }

    IN_CP(0, 0);
#pragma unroll 1
    for (int st = 0; st < 16; st++) {
        const int buf = st & 1;
        if (st < 15) { IN_CP(st + 1, buf ^ 1); CP_WAIT1(); } else { CP_WAIT0(); }
        __syncthreads();
        const float* aq = Aq + buf * 2560;
        const float* bs = Bs + buf * 2176;
#pragma unroll
        for (int k8 = 0; k8 < 16; k8 += 8) {
            uint32_t a[2][4];
#pragma unroll
            for (int mt = 0; mt < 2; mt++) {
                const int rb = wm * 32 + mt * 16;
                a[mt][0] = fb(aq[(rb + gid) * 20 + k8 + tig]);
                a[mt][1] = fb(aq[(rb + gid + 8) * 20 + k8 + tig]);
                a[mt][2] = fb(aq[(rb + gid) * 20 + k8 + tig + 4]);
                a[mt][3] = fb(aq[(rb + gid + 8) * 20 + k8 + tig + 4]);
            }
#pragma unroll
            for (int nt = 0; nt < 8; nt++) {
                const int nb = wn * 64 + nt * 8;
                uint32_t b[2] = { fb(bs[(k8 + tig) * 136 + nb + gid]),
                                  fb(bs[(k8 + tig + 4) * 136 + nb + gid]) };
                mma8(acc[0][nt], a[0], b);
                mma8(acc[1][nt], a[1], b);
            }
        }
        if (do_den) {
#pragma unroll
            for (int j = 0; j < 8; j++)
                dp = fmaf(aq[dr * 20 + dh * 8 + j], zsm[st * 16 + dh * 8 + j], dp);
        }
        __syncthreads();
    }

    if (do_den) {
        dpart[tid] = dp;
        __syncthreads();
        if (tid < 128)
            g_den[(size_t)bc * CHUNK + tid] = dpart[2 * tid] + dpart[2 * tid + 1];
    }

#pragma unroll
    for (int mt = 0; mt < 2; mt++) {
        const int t = wm * 32 + mt * 16 + gid;
#pragma unroll
        for (int nt = 0; nt < 8; nt++) {
            const int col = dv0 + wn * 64 + nt * 8 + tig * 2;
            *(float2*)(Out + (base + t) * DVV + col) =
                make_float2(acc[mt][nt][0], acc[mt][nt][1]);
            *(float2*)(Out + (base + t + 8) * DVV + col) =
                make_float2(acc[mt][nt][2], acc[mt][nt][3]);
        }
    }
}

// ---------------------------------------------------------------------------
// Kernel 4: per (b,chunk):
//   Phase A: A = tril(Pq Pk^T), K=256; tf32-round, rowsum -> den; A -> smem.
//   Phase B: intra = A @ V; Out = (intra + Out_raw) / den.
// grid 256. smem: Aq/Bk (phase A tiles, reused as V tiles), As2 [t][s] str 132.
// ---------------------------------------------------------------------------
#define CH_SMEM ((5120 + 5120 + 16896 + 256 + 128) * 4)

__global__ void __launch_bounds__(256) chunk_mma(float* __restrict__ Out)
{
    extern __shared__ float sm[];
    float* Aq  = sm;              // 2*128*20 = 5120 (phase B: V tiles 2*16*264=8448 from here)
    float* Bk  = Aq + 5120;       // 2*128*20 = 5120
    float* As2 = Bk + 5120;       // 128*132 = 16896
    float* rsh = As2 + 16896;     // 256
    float* rden = rsh + 256;      // 128
    const uint32_t aqb = su32(Aq), bkb = su32(Bk), vsb = su32(Aq);

    const int tid = threadIdx.x;
    const int lane = tid & 31, w = tid >> 5;
    const int gid = lane >> 2, tig = lane & 3;
    const int wm = w >> 1, wn = w & 1;

    const int bc = blockIdx.x;
    const size_t base = (size_t)(bc >> 5) * SEQ + (size_t)(bc & 31) * CHUNK;
    const float* pq = g_phiQ + base * MM;
    const float* pk = g_phiK + base * MM;
    const float* Vb = g_V32 + base * DVV;

    float acc[2][8][4];
#pragma unroll
    for (int mt = 0; mt < 2; mt++)
#pragma unroll
        for (int nt = 0; nt < 8; nt++)
#pragma unroll
            for (int i = 0; i < 4; i++) acc[mt][nt][i] = 0.f;

#define CA_CP(st, bf) { \
    _Pragma("unroll") \
    for (int j = 0; j < 2; j++) { \
        const int idx = tid + j * 256; \
        const int r = idx >> 2, q = (idx & 3) * 4; \
        cpa(aqb + ((bf) * 2560 + r * 20 + q) * 4, pq + r * MM + (st) * 16 + q); \
        cpa(bkb + ((bf) * 2560 + r * 20 + q) * 4, pk + r * MM + (st) * 16 + q); \
    } \
    CP_COMMIT(); }

    CA_CP(0, 0);
#pragma unroll 1
    for (int st = 0; st < 16; st++) {
        const int buf = st & 1;
        if (st < 15) { CA_CP(st + 1, buf ^ 1); CP_WAIT1(); } else { CP_WAIT0(); }
        __syncthreads();
        const float* aq = Aq + buf * 2560;
        const float* bk = Bk + buf * 2560;
#pragma unroll
        for (int k8 = 0; k8 < 16; k8 += 8) {
            uint32_t a[2][4];
#pragma unroll
            for (int mt = 0; mt < 2; mt++) {
                const int rb = wm * 32 + mt * 16;
                a[mt][0] = fb(aq[(rb + gid) * 20 + k8 + tig]);
                a[mt][1] = fb(aq[(rb + gid + 8) * 20 + k8 + tig]);
                a[mt][2] = fb(aq[(rb + gid) * 20 + k8 + tig + 4]);
                a[mt][3] = fb(aq[(rb + gid + 8) * 20 + k8 + tig + 4]);
            }
#pragma unroll
            for (int nt = 0; nt < 8; nt++) {
                const int nb = wn * 64 + nt * 8;
                uint32_t b[2] = { fb(bk[(nb + gid) * 20 + k8 + tig]),
                                  fb(bk[(nb + gid) * 20 + k8 + tig + 4]) };
                mma8(acc[0][nt], a[0], b);
                mma8(acc[1][nt], a[1], b);
            }
        }
        __syncthreads();
    }

    // start V prefetch for phase B (overlaps epilogue); Aq region reused
#define CB_CP(st, bf) { \
    _Pragma("unroll") \
    for (int j = 0; j < 4; j++) { \
        const int idx = tid + j * 256; \
        const int r = idx >> 6, qc = (idx & 63) * 4; \
        cpa(vsb + ((bf) * 4224 + r * 264 + qc) * 4, Vb + ((st) * 16 + r) * DVV + qc); \
    } \
    CP_COMMIT(); }

    CB_CP(0, 0);

    // phase A epilogue: mask, tf32-round, rowsum, stash into As2
#pragma unroll
    for (int mt = 0; mt < 2; mt++) {
        const int row = wm * 32 + mt * 16 + gid, row2 = row + 8;
        float rs1 = 0.f, rs2 = 0.f;
#pragma unroll
        for (int nt = 0; nt < 8; nt++) {
            const int col = wn * 64 + nt * 8 + tig * 2;
            float v0 = (col     <= row)  ? tf32r(acc[mt][nt][0]) : 0.f;
            float v1 = (col + 1 <= row)  ? tf32r(acc[mt][nt][1]) : 0.f;
            float v2 = (col     <= row2) ? tf32r(acc[mt][nt][2]) : 0.f;
            float v3 = (col + 1 <= row2) ? tf32r(acc[mt][nt][3]) : 0.f;
            rs1 += v0 + v1; rs2 += v2 + v3;
            *(float2*)(As2 + row * 132 + col) = make_float2(v0, v1);
            *(float2*)(As2 + row2 * 132 + col) = make_float2(v2, v3);
        }
        rs1 += __shfl_xor_sync(0xffffffffu, rs1, 1);
        rs1 += __shfl_xor_sync(0xffffffffu, rs1, 2);
        rs2 += __shfl_xor_sync(0xffffffffu, rs2, 1);
        rs2 += __shfl_xor_sync(0xffffffffu, rs2, 2);
        if (tig == 0) { rsh[wn * 128 + row] = rs1; rsh[wn * 128 + row2] = rs2; }
    }
    __syncthreads();
    if (tid < 128)
        rden[tid] = 1.f / fmaxf(g_den[(size_t)bc * CHUNK + tid] + rsh[tid] + rsh[128 + tid], 1e-6f);

    // phase B: intra = As2 @ V, 8 stages of 16 s
    float acc2[2][16][4];
#pragma unroll
    for (int mt = 0; mt < 2; mt++)
#pragma unroll
        for (int nt = 0; nt < 16; nt++)
#pragma unroll
            for (int i = 0; i < 4; i++) acc2[mt][nt][i] = 0.f;

#pragma unroll 1
    for (int st = 0; st < 8; st++) {
        const int buf = st & 1;
        if (st < 7) { CB_CP(st + 1, buf ^ 1); CP_WAIT1(); } else { CP_WAIT0(); }
        __syncthreads();
        const float* vs = Aq + buf * 4224;
#pragma unroll
        for (int k8 = 0; k8 < 16; k8 += 8) {
            const int kg = st * 16 + k8;
            uint32_t a[2][4];
#pragma unroll
            for (int mt = 0; mt < 2; mt++) {
                const int rb = wm * 32 + mt * 16;
                a[mt][0] = fb(As2[(rb + gid) * 132 + kg + tig]);
                a[mt][1] = fb(As2[(rb + gid + 8) * 132 + kg + tig]);
                a[mt][2] = fb(As2[(rb + gid) * 132 + kg + tig + 4]);
                a[mt][3] = fb(As2[(rb + gid + 8) * 132 + kg + tig + 4]);
            }
#pragma unroll
            for (int nt = 0; nt < 16; nt++) {
                const int nb = wn * 128 + nt * 8;
                uint32_t b[2] = { fb(vs[(k8 + tig) * 264 + nb + gid]),
                                  fb(vs[(k8 + tig + 4) * 264 + nb + gid]) };
                mma8(acc2[0][nt], a[0], b);
                mma8(acc2[1][nt], a[1], b);
            }
        }
        __syncthreads();
    }

    // final: Out = (intra + inter_raw) * rden
#pragma unroll
    for (int mt = 0; mt < 2; mt++) {
        const int t = wm * 32 + mt * 16 + gid, t2 = t + 8;
        const float r1 = rden[t], r2 = rden[t2];
#pragma unroll
        for (int nt = 0; nt < 16; nt++) {
            const int col = wn * 128 + nt * 8 + tig * 2;
            float2* p1 = (float2*)(Out + (base + t) * DVV + col);
            float2* p2 = (float2*)(Out + (base + t2) * DVV + col);
            float2 i1 = *p1, i2 = *p2;
            *p1 = make_float2((acc2[mt][nt][0] + i1.x) * r1, (acc2[mt][nt][1] + i1.y) * r1);
            *p2 = make_float2((acc2[mt][nt][2] + i2.x) * r2, (acc2[mt][nt][3] + i2.y) * r2);
        }
    }
}

// ---------------------------------------------------------------------------
extern "C" void kernel_launch(void* const* d_in, const int* in_sizes, int n_in,
                              void* d_out, int out_size)
{
    (void)in_sizes; (void)n_in; (void)out_size;
    const float* Q   = (const float*)d_in[0];
    const float* Kin = (const float*)d_in[1];
    const float* V   = (const float*)d_in[2];
    const float* W   = (const float*)d_in[3];
    float* Out = (float*)d_out;

    cudaFuncSetAttribute(phi_mma,   cudaFuncAttributeMaxDynamicSharedMemorySize, PHI_SMEM);
    cudaFuncSetAttribute(chunk_mma, cudaFuncAttributeMaxDynamicSharedMemorySize, CH_SMEM);

    phi_mma<<<512, 256, PHI_SMEM>>>(Q, Kin, W);
    vtrunc<<<BATCH * SEQ * DVV / 1024, 256>>>(V);
    zsum_kernel<<<BATCH * NCHUNK, 256>>>();
    scontrib_mma<<<dim3(2, 2, BATCH * NCHUNK), 256, SC_SMEM>>>();
    prefixS_kernel<<<(BATCH * MM * DVV) / 256, 256>>>();
    prefixz_kernel<<<(BATCH * MM) / 256, 256>>>();
    inter_mma<<<dim3(2, BATCH * NCHUNK), 256, IN_SMEM>>>(Out);
    chunk_mma<<<BATCH * NCHUNK, 256, CH_SMEM>>>(Out);
}